// round 10
// baseline (speedup 1.0000x reference)
#include <cuda_runtime.h>
#include <cuda_fp16.h>
#include <cstdint>

#define NN 1024
#define DD 32
#define HH 64
#define LN_EPS 1e-5f
#define PADH 68   // smem row stride (floats): max 2-way conflicts

typedef unsigned long long ull;

// ---------------- device globals ----------------
__device__ float g_hs[NN * HH];       // X @ W1[:32]
__device__ float g_hd[NN * HH];       // X @ W1[32:] + b1
__device__ float g_hsum[NN];          // row sums of g_hs
__device__ float g_dsum[NN];          // row sums of g_hd
__device__ uint2 g_w2f[8 * 4 * 32];   // fp16 W2 B-frags: [nt][kk][lane] = {b0,b1}

// ---------------- packed f32x2 helpers ----------------
__device__ __forceinline__ ull p2_add(ull a, ull b) {
    ull r; asm("add.rn.f32x2 %0, %1, %2;" : "=l"(r) : "l"(a), "l"(b)); return r;
}
__device__ __forceinline__ ull p2_fma(ull a, ull b, ull c) {
    ull r; asm("fma.rn.f32x2 %0, %1, %2, %3;" : "=l"(r) : "l"(a), "l"(b), "l"(c)); return r;
}
__device__ __forceinline__ ull p2_pack(float lo, float hi) {
    ull r; asm("mov.b64 %0, {%1, %2};" : "=l"(r) : "f"(lo), "f"(hi)); return r;
}
__device__ __forceinline__ void p2_unpack(ull v, float& lo, float& hi) {
    asm("mov.b64 {%0, %1}, %2;" : "=f"(lo), "=f"(hi) : "l"(v));
}
__device__ __forceinline__ uint32_t pack_h2(float a, float b) {
    __half2 t = __floats2half2_rn(a, b);
    return *reinterpret_cast<uint32_t*>(&t);
}
__device__ __forceinline__ void mma_f16(float* c, uint32_t a0, uint32_t a1,
                                        uint32_t a2, uint32_t a3,
                                        uint32_t b0, uint32_t b1) {
    asm volatile(
        "mma.sync.aligned.m16n8k16.row.col.f32.f16.f16.f32 "
        "{%0,%1,%2,%3}, {%4,%5,%6,%7}, {%8,%9}, {%0,%1,%2,%3};"
        : "+f"(c[0]), "+f"(c[1]), "+f"(c[2]), "+f"(c[3])
        : "r"(a0), "r"(a1), "r"(a2), "r"(a3), "r"(b0), "r"(b1));
}
__device__ __forceinline__ float qred(float v) {
    v += __shfl_xor_sync(0xffffffffu, v, 1);
    v += __shfl_xor_sync(0xffffffffu, v, 2);
    return v;
}
__device__ __forceinline__ float wred32(float v) {
    #pragma unroll
    for (int s = 16; s > 0; s >>= 1) v += __shfl_xor_sync(0xffffffffu, v, s);
    return v;
}

// ---------------- merged prep ----------------
__global__ void prep_all(const float* __restrict__ X,
                         const float* __restrict__ W1,
                         const float* __restrict__ b1,
                         const float* __restrict__ W2) {
    if (blockIdx.x < 256) {
        __shared__ float xs[4][DD];
        __shared__ float red[4][HH];
        int sub = threadIdx.x >> 6;
        int n = threadIdx.x & 63;
        int i = blockIdx.x * 4 + sub;
        if (n < DD) xs[sub][n] = X[i * DD + n];
        __syncthreads();
        float hs = 0.f, hd = b1[n];
        #pragma unroll
        for (int d = 0; d < DD; d++) {
            float xv = xs[sub][d];
            hs = fmaf(xv, W1[d * HH + n], hs);
            hd = fmaf(xv, W1[(DD + d) * HH + n], hd);
        }
        g_hs[i * HH + n] = hs;
        g_hd[i * HH + n] = hd;
        red[sub][n] = hs;
        __syncthreads();
        if (n < 32) {
            float v = red[sub][n] + red[sub][n + 32];
            v = wred32(v);
            if (n == 0) g_hsum[i] = v;
        }
        __syncthreads();
        red[sub][n] = hd;
        __syncthreads();
        if (n < 32) {
            float v = red[sub][n] + red[sub][n + 32];
            v = wred32(v);
            if (n == 0) g_dsum[i] = v;
        }
    } else {
        int t = (blockIdx.x - 256) * 256 + threadIdx.x;
        if (t >= 1024) return;
        int lane = t & 31;
        int kk = (t >> 5) & 3;
        int nt = t >> 7;
        int n  = nt * 8 + (lane >> 2);
        int kq = kk * 16 + (lane & 3) * 2;
        uint2 r;
        r.x = pack_h2(W2[kq * HH + n],       W2[(kq + 1) * HH + n]);
        r.y = pack_h2(W2[(kq + 8) * HH + n], W2[(kq + 9) * HH + n]);
        g_w2f[t] = r;
    }
}

// ---------------- main pair kernel ----------------
__global__ __launch_bounds__(128, 5) void pair_kernel(
    const float* __restrict__ g1, const float* __restrict__ be1,
    const float* __restrict__ b2, const float* __restrict__ g2,
    const float* __restrict__ be2, const float* __restrict__ W3,
    const float* __restrict__ b3, float* __restrict__ out) {
    __shared__ uint2 s_bf[8 * 4 * 32];
    __shared__ __align__(16) float s_hd[16 * PADH];
    __shared__ __align__(16) float s_hs[8 * PADH];
    // fragment-ordered parameter banks, 144B qc-pitch => conflict-free LDS.128
    __shared__ __align__(16) ulonglong2 s_e1[4][9];    // [qc][ci]: {g1 pair, be1 pair} at prologue col
    __shared__ __align__(16) ulonglong2 s_e2[4][9];    // [qc][nt]: {g2 pair, be2 pair} at frag col
    __shared__ __align__(16) ulonglong2 s_w3b[4][9];   // [qc][nt]: {w3 pair, b2 pair} at frag col
    __shared__ float s_S[8], s_T[16], s_b3;

    int tid = threadIdx.x;
    int w = tid >> 5, lane = tid & 31;
    int qr = lane >> 2, qc = lane & 3;
    int bx = blockIdx.x, by = blockIdx.y;

    #pragma unroll
    for (int idx = tid; idx < 1024; idx += 128) s_bf[idx] = g_w2f[idx];
    #pragma unroll
    for (int idx = tid; idx < 16 * 64; idx += 128) {
        int r = idx >> 6, c = idx & 63;
        s_hd[r * PADH + c] = g_hd[(bx * 16 + r) * HH + c];
    }
    #pragma unroll
    for (int idx = tid; idx < 8 * 64; idx += 128) {
        int r = idx >> 6, c = idx & 63;
        s_hs[r * PADH + c] = g_hs[(by * 8 + r) * HH + c];
    }
    if (tid < 32) {
        int qcf = tid >> 3, e = tid & 7;
        int cp = (e >> 1) * 16 + (e & 1) * 8 + qcf * 2;   // prologue column
        int cf = e * 8 + qcf * 2;                          // fragment column
        ulonglong2 p;
        p.x = p2_pack(g1[cp],  g1[cp + 1]);
        p.y = p2_pack(be1[cp], be1[cp + 1]);
        s_e1[qcf][e] = p;
        p.x = p2_pack(g2[cf],  g2[cf + 1]);
        p.y = p2_pack(be2[cf], be2[cf + 1]);
        s_e2[qcf][e] = p;
        p.x = p2_pack(W3[cf], W3[cf + 1]);
        p.y = p2_pack(b2[cf], b2[cf + 1]);
        s_w3b[qcf][e] = p;
    }
    if (tid < 8)  s_S[tid] = g_hsum[by * 8 + tid];
    if (tid < 16) s_T[tid] = g_dsum[bx * 16 + tid];
    if (tid == 0) s_b3 = b3[0];
    __syncthreads();

    const float* hdr1 = s_hd + qr * PADH;
    const float* hdr2 = s_hd + (qr + 8) * PADH;
    float Tv1 = s_T[qr], Tv2 = s_T[qr + 8];

    // ---- prologue: packed LN1 -> fp16 A frags ----
    uint32_t af[2][4][4];
    #pragma unroll
    for (int mt = 0; mt < 2; mt++) {
        const float* hsr = s_hs + (w * 2 + mt) * PADH;
        ull a[8];
        #pragma unroll
        for (int ci = 0; ci < 8; ci++) {
            int c = (ci >> 1) * 16 + (ci & 1) * 8 + qc * 2;
            a[ci] = *reinterpret_cast<const ull*>(hsr + c);   // quad-broadcast, cheap
        }
        float Sv = s_S[w * 2 + mt];
        #pragma unroll
        for (int rr = 0; rr < 2; rr++) {
            const float* hdr = rr ? hdr2 : hdr1;
            float Tv = rr ? Tv2 : Tv1;
            ull x[8];
            ull s2p = 0ull;
            #pragma unroll
            for (int ci = 0; ci < 8; ci++) {
                int c = (ci >> 1) * 16 + (ci & 1) * 8 + qc * 2;
                ull d = *reinterpret_cast<const ull*>(hdr + c);
                x[ci] = p2_add(a[ci], d);
                s2p = p2_fma(x[ci], x[ci], s2p);
            }
            float lo, hi;
            p2_unpack(s2p, lo, hi);
            float s2 = qred(lo + hi);
            float mu = (Sv + Tv) * (1.f / HH);
            float rs = rsqrtf(s2 * (1.f / HH) - mu * mu + LN_EPS);
            ull rsp = p2_pack(rs, rs);
            ull nmp = p2_pack(-mu * rs, -mu * rs);
            #pragma unroll
            for (int ci = 0; ci < 8; ci++) {
                int kk = ci >> 1, h = ci & 1;
                ulonglong2 P = s_e1[qc][ci];               // conflict-free LDS.128
                ull v = p2_fma(p2_fma(x[ci], rsp, nmp), P.x, P.y);
                float va, vb;
                p2_unpack(v, va, vb);
                af[mt][kk][h * 2 + rr] = pack_h2(fmaxf(va, 0.f), fmaxf(vb, 0.f));
            }
        }
    }

    // ---- fused MMA, acc initialized with b2 ----
    float acc[2][8][4];
    #pragma unroll
    for (int nt = 0; nt < 8; nt++) {
        ull b2p = s_w3b[qc][nt].y;
        float bxv, byv;
        p2_unpack(b2p, bxv, byv);
        #pragma unroll
        for (int mt = 0; mt < 2; mt++) {
            acc[mt][nt][0] = bxv; acc[mt][nt][1] = byv;
            acc[mt][nt][2] = bxv; acc[mt][nt][3] = byv;
        }
    }
    #pragma unroll
    for (int nt = 0; nt < 8; nt++) {
        #pragma unroll
        for (int kk = 0; kk < 4; kk++) {
            uint2 B = s_bf[(nt * 4 + kk) * 32 + lane];
            mma_f16(acc[0][nt], af[0][kk][0], af[0][kk][1], af[0][kk][2], af[0][kk][3], B.x, B.y);
            mma_f16(acc[1][nt], af[1][kk][0], af[1][kk][1], af[1][kk][2], af[1][kk][3], B.x, B.y);
        }
    }

    // ---- epilogue per mtile ----
    #pragma unroll
    for (int mt = 0; mt < 2; mt++) {
        int i  = by * 8 + w * 2 + mt;
        int j1 = bx * 16 + qr;

        ull t11p = 0ull, t12p = 0ull, t21p = 0ull, t22p = 0ull;
        #pragma unroll
        for (int nt = 0; nt < 8; nt++) {
            ull ua = p2_pack(acc[mt][nt][0], acc[mt][nt][1]);
            ull ub = p2_pack(acc[mt][nt][2], acc[mt][nt][3]);
            t11p = p2_add(t11p, ua); t12p = p2_fma(ua, ua, t12p);
            t21p = p2_add(t21p, ub); t22p = p2_fma(ub, ub, t22p);
        }
        float lo, hi;
        p2_unpack(t11p, lo, hi); float t11 = qred(lo + hi);
        p2_unpack(t12p, lo, hi); float t12 = qred(lo + hi);
        p2_unpack(t21p, lo, hi); float t21 = qred(lo + hi);
        p2_unpack(t22p, lo, hi); float t22 = qred(lo + hi);
        float m1 = t11 * (1.f / HH);
        float r1 = rsqrtf(t12 * (1.f / HH) - m1 * m1 + LN_EPS);
        float m2 = t21 * (1.f / HH);
        float r2 = rsqrtf(t22 * (1.f / HH) - m2 * m2 + LN_EPS);
        ull r1p = p2_pack(r1, r1), nm1p = p2_pack(-m1 * r1, -m1 * r1);
        ull r2p = p2_pack(r2, r2), nm2p = p2_pack(-m2 * r2, -m2 * r2);

        ull d1p = 0ull, d2p = 0ull;
        #pragma unroll
        for (int nt = 0; nt < 8; nt++) {
            ulonglong2 P = s_e2[qc][nt];                  // conflict-free LDS.128
            ull w3p = s_w3b[qc][nt].x;
            ull ua = p2_pack(acc[mt][nt][0], acc[mt][nt][1]);
            ull ub = p2_pack(acc[mt][nt][2], acc[mt][nt][3]);
            float za, zb;
            ull z1 = p2_fma(p2_fma(ua, r1p, nm1p), P.x, P.y);
            p2_unpack(z1, za, zb);
            d1p = p2_fma(p2_pack(fmaxf(za, 0.f), fmaxf(zb, 0.f)), w3p, d1p);
            ull z2 = p2_fma(p2_fma(ub, r2p, nm2p), P.x, P.y);
            p2_unpack(z2, za, zb);
            d2p = p2_fma(p2_pack(fmaxf(za, 0.f), fmaxf(zb, 0.f)), w3p, d2p);
        }
        p2_unpack(d1p, lo, hi); float d1 = qred(lo + hi);
        p2_unpack(d2p, lo, hi); float d2 = qred(lo + hi);
        if (qc == 0) {
            out[i * NN + j1]     = 1.f / (1.f + __expf(-(d1 + s_b3)));
            out[i * NN + j1 + 8] = 1.f / (1.f + __expf(-(d2 + s_b3)));
        }
    }
}

// ---------------- launch ----------------
extern "C" void kernel_launch(void* const* d_in, const int* in_sizes, int n_in,
                              void* d_out, int out_size) {
    const float* X   = (const float*)d_in[0];
    const float* W1  = (const float*)d_in[1];
    const float* b1  = (const float*)d_in[2];
    const float* g1  = (const float*)d_in[3];
    const float* be1 = (const float*)d_in[4];
    const float* W2  = (const float*)d_in[5];
    const float* b2  = (const float*)d_in[6];
    const float* g2  = (const float*)d_in[7];
    const float* be2 = (const float*)d_in[8];
    const float* W3  = (const float*)d_in[9];
    const float* b3  = (const float*)d_in[10];
    float* out = (float*)d_out;

    prep_all<<<260, 256>>>(X, W1, b1, W2);
    dim3 grid(NN / 16, NN / 8);
    pair_kernel<<<grid, 128>>>(g1, be1, b2, g2, be2, W3, b3, out);
}

// round 11
// speedup vs baseline: 1.1279x; 1.1279x over previous
#include <cuda_runtime.h>
#include <cuda_fp16.h>
#include <cstdint>

#define NN 1024
#define DD 32
#define HH 64
#define LN_EPS 1e-5f

typedef unsigned long long ull;

// ---------------- device globals ----------------
__device__ float g_hs[NN * HH];       // X @ W1[:32]
__device__ float g_hd[NN * HH];       // X @ W1[32:] + b1
__device__ float g_hsum[NN];          // row sums of g_hs
__device__ float g_dsum[NN];          // row sums of g_hd
__device__ uint2 g_w2f[8 * 4 * 32];   // fp16 W2 B-frags: [nt][kk][lane] = {b0,b1}

// ---------------- packed f32x2 helpers ----------------
__device__ __forceinline__ ull p2_add(ull a, ull b) {
    ull r; asm("add.rn.f32x2 %0, %1, %2;" : "=l"(r) : "l"(a), "l"(b)); return r;
}
__device__ __forceinline__ ull p2_fma(ull a, ull b, ull c) {
    ull r; asm("fma.rn.f32x2 %0, %1, %2, %3;" : "=l"(r) : "l"(a), "l"(b), "l"(c)); return r;
}
__device__ __forceinline__ ull p2_pack(float lo, float hi) {
    ull r; asm("mov.b64 %0, {%1, %2};" : "=l"(r) : "f"(lo), "f"(hi)); return r;
}
__device__ __forceinline__ void p2_unpack(ull v, float& lo, float& hi) {
    asm("mov.b64 {%0, %1}, %2;" : "=f"(lo), "=f"(hi) : "l"(v));
}
__device__ __forceinline__ uint32_t pack_h2(float a, float b) {
    __half2 t = __floats2half2_rn(a, b);
    return *reinterpret_cast<uint32_t*>(&t);
}
__device__ __forceinline__ void mma_f16(float* c, uint32_t a0, uint32_t a1,
                                        uint32_t a2, uint32_t a3,
                                        uint32_t b0, uint32_t b1) {
    asm volatile(
        "mma.sync.aligned.m16n8k16.row.col.f32.f16.f16.f32 "
        "{%0,%1,%2,%3}, {%4,%5,%6,%7}, {%8,%9}, {%0,%1,%2,%3};"
        : "+f"(c[0]), "+f"(c[1]), "+f"(c[2]), "+f"(c[3])
        : "r"(a0), "r"(a1), "r"(a2), "r"(a3), "r"(b0), "r"(b1));
}
__device__ __forceinline__ float qred(float v) {
    v += __shfl_xor_sync(0xffffffffu, v, 1);
    v += __shfl_xor_sync(0xffffffffu, v, 2);
    return v;
}
__device__ __forceinline__ float wred32(float v) {
    #pragma unroll
    for (int s = 16; s > 0; s >>= 1) v += __shfl_xor_sync(0xffffffffu, v, s);
    return v;
}
__device__ __forceinline__ ull ldg_ull(const float* p) {
    return *reinterpret_cast<const ull*>(p);
}

// ---------------- merged prep ----------------
__global__ void prep_all(const float* __restrict__ X,
                         const float* __restrict__ W1,
                         const float* __restrict__ b1,
                         const float* __restrict__ W2) {
    if (blockIdx.x < 256) {
        __shared__ float xs[4][DD];
        __shared__ float red[4][HH];
        int sub = threadIdx.x >> 6;
        int n = threadIdx.x & 63;
        int i = blockIdx.x * 4 + sub;
        if (n < DD) xs[sub][n] = X[i * DD + n];
        __syncthreads();
        float hs = 0.f, hd = b1[n];
        #pragma unroll
        for (int d = 0; d < DD; d++) {
            float xv = xs[sub][d];
            hs = fmaf(xv, W1[d * HH + n], hs);
            hd = fmaf(xv, W1[(DD + d) * HH + n], hd);
        }
        g_hs[i * HH + n] = hs;
        g_hd[i * HH + n] = hd;
        red[sub][n] = hs;
        __syncthreads();
        if (n < 32) {
            float v = red[sub][n] + red[sub][n + 32];
            v = wred32(v);
            if (n == 0) g_hsum[i] = v;
        }
        __syncthreads();
        red[sub][n] = hd;
        __syncthreads();
        if (n < 32) {
            float v = red[sub][n] + red[sub][n + 32];
            v = wred32(v);
            if (n == 0) g_dsum[i] = v;
        }
    } else {
        int t = (blockIdx.x - 256) * 256 + threadIdx.x;
        if (t >= 1024) return;
        int lane = t & 31;
        int kk = (t >> 5) & 3;
        int nt = t >> 7;
        int n  = nt * 8 + (lane >> 2);
        int kq = kk * 16 + (lane & 3) * 2;
        uint2 r;
        r.x = pack_h2(W2[kq * HH + n],       W2[(kq + 1) * HH + n]);
        r.y = pack_h2(W2[(kq + 8) * HH + n], W2[(kq + 9) * HH + n]);
        g_w2f[t] = r;
    }
}

// ---------------- main pair kernel: ZERO smem, everything via L1 ----------------
__global__ __launch_bounds__(128) void pair_kernel(
    const float* __restrict__ g1, const float* __restrict__ be1,
    const float* __restrict__ b2, const float* __restrict__ g2,
    const float* __restrict__ be2, const float* __restrict__ W3,
    const float* __restrict__ b3, float* __restrict__ out) {
    int tid = threadIdx.x;
    int w = tid >> 5, lane = tid & 31;
    int qr = lane >> 2, qc = lane & 3;
    int bx = blockIdx.x, by = blockIdx.y;

    // ---- hd rows for this thread's two j values (register-cached, L1-backed) ----
    const float* hdr1 = g_hd + (bx * 16 + qr) * HH;
    const float* hdr2 = g_hd + (bx * 16 + qr + 8) * HH;
    ull dA[8], dB[8];
    #pragma unroll
    for (int ci = 0; ci < 8; ci++) {
        int c = (ci >> 1) * 16 + (ci & 1) * 8 + qc * 2;
        dA[ci] = ldg_ull(hdr1 + c);
        dB[ci] = ldg_ull(hdr2 + c);
    }
    float Tv1 = g_dsum[bx * 16 + qr];
    float Tv2 = g_dsum[bx * 16 + qr + 8];

    // ---- prologue: packed LN1 -> fp16 A frags ----
    uint32_t af[2][4][4];
    #pragma unroll
    for (int mt = 0; mt < 2; mt++) {
        const float* hsr = g_hs + (by * 8 + w * 2 + mt) * HH;
        ull a[8];
        #pragma unroll
        for (int ci = 0; ci < 8; ci++) {
            int c = (ci >> 1) * 16 + (ci & 1) * 8 + qc * 2;
            a[ci] = ldg_ull(hsr + c);
        }
        float Sv = g_hsum[by * 8 + w * 2 + mt];
        #pragma unroll
        for (int rr = 0; rr < 2; rr++) {
            const ull* D = rr ? dB : dA;
            float Tv = rr ? Tv2 : Tv1;
            ull x[8];
            ull s2p = 0ull;
            #pragma unroll
            for (int ci = 0; ci < 8; ci++) {
                x[ci] = p2_add(a[ci], D[ci]);
                s2p = p2_fma(x[ci], x[ci], s2p);
            }
            float lo, hi;
            p2_unpack(s2p, lo, hi);
            float s2 = qred(lo + hi);
            float mu = (Sv + Tv) * (1.f / HH);
            float rs = rsqrtf(s2 * (1.f / HH) - mu * mu + LN_EPS);
            ull rsp = p2_pack(rs, rs);
            ull nmp = p2_pack(-mu * rs, -mu * rs);
            #pragma unroll
            for (int ci = 0; ci < 8; ci++) {
                int kk = ci >> 1, h = ci & 1;
                int c = kk * 16 + h * 8 + qc * 2;
                ull gp = ldg_ull(g1 + c);
                ull bp = ldg_ull(be1 + c);
                ull v = p2_fma(p2_fma(x[ci], rsp, nmp), gp, bp);
                float va, vb;
                p2_unpack(v, va, vb);
                af[mt][kk][h * 2 + rr] = pack_h2(fmaxf(va, 0.f), fmaxf(vb, 0.f));
            }
        }
    }

    // ---- fused MMA, acc initialized with b2 (read straight from L1) ----
    float acc[2][8][4];
    #pragma unroll
    for (int nt = 0; nt < 8; nt++) {
        int c = nt * 8 + qc * 2;
        ull b2p = ldg_ull(b2 + c);
        float bxv, byv;
        p2_unpack(b2p, bxv, byv);
        #pragma unroll
        for (int mt = 0; mt < 2; mt++) {
            acc[mt][nt][0] = bxv; acc[mt][nt][1] = byv;
            acc[mt][nt][2] = bxv; acc[mt][nt][3] = byv;
        }
    }
    #pragma unroll
    for (int nt = 0; nt < 8; nt++) {
        #pragma unroll
        for (int kk = 0; kk < 4; kk++) {
            uint2 B = g_w2f[(nt * 4 + kk) * 32 + lane];   // fully coalesced, L1-hot
            mma_f16(acc[0][nt], af[0][kk][0], af[0][kk][1], af[0][kk][2], af[0][kk][3], B.x, B.y);
            mma_f16(acc[1][nt], af[1][kk][0], af[1][kk][1], af[1][kk][2], af[1][kk][3], B.x, B.y);
        }
    }

    // ---- epilogue per mtile ----
    #pragma unroll
    for (int mt = 0; mt < 2; mt++) {
        int i  = by * 8 + w * 2 + mt;
        int j1 = bx * 16 + qr;

        ull u1p[8], u2p[8];
        ull t11p = 0ull, t12p = 0ull, t21p = 0ull, t22p = 0ull;
        #pragma unroll
        for (int nt = 0; nt < 8; nt++) {
            ull ua = p2_pack(acc[mt][nt][0], acc[mt][nt][1]);
            ull ub = p2_pack(acc[mt][nt][2], acc[mt][nt][3]);
            u1p[nt] = ua; u2p[nt] = ub;
            t11p = p2_add(t11p, ua); t12p = p2_fma(ua, ua, t12p);
            t21p = p2_add(t21p, ub); t22p = p2_fma(ub, ub, t22p);
        }
        float lo, hi;
        p2_unpack(t11p, lo, hi); float t11 = qred(lo + hi);
        p2_unpack(t12p, lo, hi); float t12 = qred(lo + hi);
        p2_unpack(t21p, lo, hi); float t21 = qred(lo + hi);
        p2_unpack(t22p, lo, hi); float t22 = qred(lo + hi);
        float m1 = t11 * (1.f / HH);
        float r1 = rsqrtf(t12 * (1.f / HH) - m1 * m1 + LN_EPS);
        float m2 = t21 * (1.f / HH);
        float r2 = rsqrtf(t22 * (1.f / HH) - m2 * m2 + LN_EPS);
        ull r1p = p2_pack(r1, r1), nm1p = p2_pack(-m1 * r1, -m1 * r1);
        ull r2p = p2_pack(r2, r2), nm2p = p2_pack(-m2 * r2, -m2 * r2);

        ull d1p = 0ull, d2p = 0ull;
        #pragma unroll
        for (int nt = 0; nt < 8; nt++) {
            int c = nt * 8 + qc * 2;
            ull g2p  = ldg_ull(g2 + c);
            ull be2p = ldg_ull(be2 + c);
            ull w3p  = ldg_ull(W3 + c);
            float za, zb;
            ull z1 = p2_fma(p2_fma(u1p[nt], r1p, nm1p), g2p, be2p);
            p2_unpack(z1, za, zb);
            d1p = p2_fma(p2_pack(fmaxf(za, 0.f), fmaxf(zb, 0.f)), w3p, d1p);
            ull z2 = p2_fma(p2_fma(u2p[nt], r2p, nm2p), g2p, be2p);
            p2_unpack(z2, za, zb);
            d2p = p2_fma(p2_pack(fmaxf(za, 0.f), fmaxf(zb, 0.f)), w3p, d2p);
        }
        p2_unpack(d1p, lo, hi); float d1 = qred(lo + hi);
        p2_unpack(d2p, lo, hi); float d2 = qred(lo + hi);
        if (qc == 0) {
            float b3v = b3[0];
            out[i * NN + j1]     = 1.f / (1.f + __expf(-(d1 + b3v)));
            out[i * NN + j1 + 8] = 1.f / (1.f + __expf(-(d2 + b3v)));
        }
    }
}

// ---------------- launch ----------------
extern "C" void kernel_launch(void* const* d_in, const int* in_sizes, int n_in,
                              void* d_out, int out_size) {
    const float* X   = (const float*)d_in[0];
    const float* W1  = (const float*)d_in[1];
    const float* b1  = (const float*)d_in[2];
    const float* g1  = (const float*)d_in[3];
    const float* be1 = (const float*)d_in[4];
    const float* W2  = (const float*)d_in[5];
    const float* b2  = (const float*)d_in[6];
    const float* g2  = (const float*)d_in[7];
    const float* be2 = (const float*)d_in[8];
    const float* W3  = (const float*)d_in[9];
    const float* b3  = (const float*)d_in[10];
    float* out = (float*)d_out;

    prep_all<<<260, 256>>>(X, W1, b1, W2);
    dim3 grid(NN / 16, NN / 8);
    pair_kernel<<<grid, 128>>>(g1, be1, b2, g2, be2, W3, b3, out);
}

// round 12
// speedup vs baseline: 1.2921x; 1.1456x over previous
#include <cuda_runtime.h>
#include <cuda_fp16.h>
#include <cstdint>

#define NN 1024
#define DD 32
#define HH 64
#define LN_EPS 1e-5f
#define PADH 68   // smem row stride (floats): max 2-way conflicts

typedef unsigned long long ull;

// ---------------- device globals ----------------
__device__ float g_hs[NN * HH];       // X @ W1[:32]
__device__ float g_hd[NN * HH];       // X @ W1[32:] + b1
__device__ float g_hsum[NN];          // row sums of g_hs
__device__ float g_dsum[NN];          // row sums of g_hd
__device__ uint2 g_w2f[8 * 4 * 32];   // fp16 W2 B-frags: [nt][kk][lane] = {b0,b1}

// ---------------- packed f32x2 helpers ----------------
__device__ __forceinline__ ull p2_add(ull a, ull b) {
    ull r; asm("add.rn.f32x2 %0, %1, %2;" : "=l"(r) : "l"(a), "l"(b)); return r;
}
__device__ __forceinline__ ull p2_fma(ull a, ull b, ull c) {
    ull r; asm("fma.rn.f32x2 %0, %1, %2, %3;" : "=l"(r) : "l"(a), "l"(b), "l"(c)); return r;
}
__device__ __forceinline__ ull p2_pack(float lo, float hi) {
    ull r; asm("mov.b64 %0, {%1, %2};" : "=l"(r) : "f"(lo), "f"(hi)); return r;
}
__device__ __forceinline__ void p2_unpack(ull v, float& lo, float& hi) {
    asm("mov.b64 {%0, %1}, %2;" : "=f"(lo), "=f"(hi) : "l"(v));
}
__device__ __forceinline__ uint32_t pack_h2(float a, float b) {
    __half2 t = __floats2half2_rn(a, b);
    return *reinterpret_cast<uint32_t*>(&t);
}
__device__ __forceinline__ void mma_f16(float* c, uint32_t a0, uint32_t a1,
                                        uint32_t a2, uint32_t a3,
                                        uint32_t b0, uint32_t b1) {
    asm volatile(
        "mma.sync.aligned.m16n8k16.row.col.f32.f16.f16.f32 "
        "{%0,%1,%2,%3}, {%4,%5,%6,%7}, {%8,%9}, {%0,%1,%2,%3};"
        : "+f"(c[0]), "+f"(c[1]), "+f"(c[2]), "+f"(c[3])
        : "r"(a0), "r"(a1), "r"(a2), "r"(a3), "r"(b0), "r"(b1));
}
__device__ __forceinline__ float qred(float v) {
    v += __shfl_xor_sync(0xffffffffu, v, 1);
    v += __shfl_xor_sync(0xffffffffu, v, 2);
    return v;
}
__device__ __forceinline__ float wred32(float v) {
    #pragma unroll
    for (int s = 16; s > 0; s >>= 1) v += __shfl_xor_sync(0xffffffffu, v, s);
    return v;
}

// ---------------- merged prep ----------------
__global__ void prep_all(const float* __restrict__ X,
                         const float* __restrict__ W1,
                         const float* __restrict__ b1,
                         const float* __restrict__ W2) {
    if (blockIdx.x < 256) {
        __shared__ float xs[4][DD];
        __shared__ float red[4][HH];
        int sub = threadIdx.x >> 6;
        int n = threadIdx.x & 63;
        int i = blockIdx.x * 4 + sub;
        if (n < DD) xs[sub][n] = X[i * DD + n];
        __syncthreads();
        float hs = 0.f, hd = b1[n];
        #pragma unroll
        for (int d = 0; d < DD; d++) {
            float xv = xs[sub][d];
            hs = fmaf(xv, W1[d * HH + n], hs);
            hd = fmaf(xv, W1[(DD + d) * HH + n], hd);
        }
        g_hs[i * HH + n] = hs;
        g_hd[i * HH + n] = hd;
        red[sub][n] = hs;
        __syncthreads();
        if (n < 32) {
            float v = red[sub][n] + red[sub][n + 32];
            v = wred32(v);
            if (n == 0) g_hsum[i] = v;
        }
        __syncthreads();
        red[sub][n] = hd;
        __syncthreads();
        if (n < 32) {
            float v = red[sub][n] + red[sub][n + 32];
            v = wred32(v);
            if (n == 0) g_dsum[i] = v;
        }
    } else {
        int t = (blockIdx.x - 256) * 256 + threadIdx.x;
        if (t >= 1024) return;
        int lane = t & 31;
        int kk = (t >> 5) & 3;
        int nt = t >> 7;
        int n  = nt * 8 + (lane >> 2);
        int kq = kk * 16 + (lane & 3) * 2;
        uint2 r;
        r.x = pack_h2(W2[kq * HH + n],       W2[(kq + 1) * HH + n]);
        r.y = pack_h2(W2[(kq + 8) * HH + n], W2[(kq + 9) * HH + n]);
        g_w2f[t] = r;
    }
}

// ---------------- main pair kernel ----------------
__global__ __launch_bounds__(128, 4) void pair_kernel(
    const float* __restrict__ g1, const float* __restrict__ be1,
    const float* __restrict__ b2, const float* __restrict__ g2,
    const float* __restrict__ be2, const float* __restrict__ W3,
    const float* __restrict__ b3, float* __restrict__ out) {
    __shared__ uint2 s_bf[8 * 4 * 32];
    __shared__ __align__(16) float s_hd[16 * PADH];
    __shared__ __align__(16) float s_hs[8 * PADH];
    __shared__ __align__(8) float s_g1[HH];
    __shared__ __align__(8) float s_be1[HH];
    __shared__ __align__(8) float s_b2[HH];
    __shared__ __align__(8) float s_g2[HH];
    __shared__ __align__(8) float s_be2[HH];
    __shared__ __align__(8) float s_w3[HH];
    __shared__ float s_S[8], s_T[16], s_b3;

    int tid = threadIdx.x;
    int w = tid >> 5, lane = tid & 31;
    int qr = lane >> 2, qc = lane & 3;
    int bx = blockIdx.x, by = blockIdx.y;

    #pragma unroll
    for (int idx = tid; idx < 1024; idx += 128) s_bf[idx] = g_w2f[idx];
    #pragma unroll
    for (int idx = tid; idx < 16 * 64; idx += 128) {
        int r = idx >> 6, c = idx & 63;
        s_hd[r * PADH + c] = g_hd[(bx * 16 + r) * HH + c];
    }
    #pragma unroll
    for (int idx = tid; idx < 8 * 64; idx += 128) {
        int r = idx >> 6, c = idx & 63;
        s_hs[r * PADH + c] = g_hs[(by * 8 + r) * HH + c];
    }
    if (tid < HH) {
        s_g1[tid]  = g1[tid];
        s_be1[tid] = be1[tid];
        s_b2[tid]  = b2[tid];
        s_g2[tid]  = g2[tid];
        s_be2[tid] = be2[tid];
        s_w3[tid]  = W3[tid];
    }
    if (tid < 8)  s_S[tid] = g_hsum[by * 8 + tid];
    if (tid < 16) s_T[tid] = g_dsum[bx * 16 + tid];
    if (tid == 0) s_b3 = b3[0];
    __syncthreads();

    // ---- hd rows in registers (reused across all 4 combos) ----
    const float* hdr1 = s_hd + qr * PADH;
    const float* hdr2 = s_hd + (qr + 8) * PADH;
    ull dA[8], dB[8];
    #pragma unroll
    for (int ci = 0; ci < 8; ci++) {
        int c = (ci >> 1) * 16 + (ci & 1) * 8 + qc * 2;
        dA[ci] = *reinterpret_cast<const ull*>(hdr1 + c);
        dB[ci] = *reinterpret_cast<const ull*>(hdr2 + c);
    }
    const float* hsr0 = s_hs + (w * 2) * PADH;
    const float* hsr1 = s_hs + (w * 2 + 1) * PADH;

    // ---- Phase A: four independent packed sum-of-squares, batched reductions ----
    ull s2p0 = 0ull, s2p1 = 0ull, s2p2 = 0ull, s2p3 = 0ull;
    #pragma unroll
    for (int ci = 0; ci < 8; ci++) {
        int c = (ci >> 1) * 16 + (ci & 1) * 8 + qc * 2;
        ull a0 = *reinterpret_cast<const ull*>(hsr0 + c);   // quad-broadcast
        ull a1 = *reinterpret_cast<const ull*>(hsr1 + c);
        ull x;
        x = p2_add(a0, dA[ci]); s2p0 = p2_fma(x, x, s2p0);
        x = p2_add(a0, dB[ci]); s2p1 = p2_fma(x, x, s2p1);
        x = p2_add(a1, dA[ci]); s2p2 = p2_fma(x, x, s2p2);
        x = p2_add(a1, dB[ci]); s2p3 = p2_fma(x, x, s2p3);
    }
    float lo, hi;
    p2_unpack(s2p0, lo, hi); float q0 = lo + hi;
    p2_unpack(s2p1, lo, hi); float q1 = lo + hi;
    p2_unpack(s2p2, lo, hi); float q2 = lo + hi;
    p2_unpack(s2p3, lo, hi); float q3 = lo + hi;
    q0 = qred(q0); q1 = qred(q1); q2 = qred(q2); q3 = qred(q3);   // ILP-batched
    float Sv0 = s_S[w * 2], Sv1 = s_S[w * 2 + 1];
    float Tv1 = s_T[qr],    Tv2 = s_T[qr + 8];
    float mu0 = (Sv0 + Tv1) * (1.f / HH);
    float mu1 = (Sv0 + Tv2) * (1.f / HH);
    float mu2 = (Sv1 + Tv1) * (1.f / HH);
    float mu3 = (Sv1 + Tv2) * (1.f / HH);
    float rs0 = rsqrtf(q0 * (1.f / HH) - mu0 * mu0 + LN_EPS);
    float rs1 = rsqrtf(q1 * (1.f / HH) - mu1 * mu1 + LN_EPS);
    float rs2 = rsqrtf(q2 * (1.f / HH) - mu2 * mu2 + LN_EPS);
    float rs3 = rsqrtf(q3 * (1.f / HH) - mu3 * mu3 + LN_EPS);
    ull rsp0 = p2_pack(rs0, rs0), nmp0 = p2_pack(-mu0 * rs0, -mu0 * rs0);
    ull rsp1 = p2_pack(rs1, rs1), nmp1 = p2_pack(-mu1 * rs1, -mu1 * rs1);
    ull rsp2 = p2_pack(rs2, rs2), nmp2 = p2_pack(-mu2 * rs2, -mu2 * rs2);
    ull rsp3 = p2_pack(rs3, rs3), nmp3 = p2_pack(-mu3 * rs3, -mu3 * rs3);

    // ---- Phase B: apply, column-outer so gp/bp are loaded ONCE per column ----
    uint32_t af[2][4][4];
    #pragma unroll
    for (int ci = 0; ci < 8; ci++) {
        int kk = ci >> 1, h = ci & 1;
        int c = kk * 16 + h * 8 + qc * 2;
        ull gp = *reinterpret_cast<const ull*>(s_g1 + c);
        ull bp = *reinterpret_cast<const ull*>(s_be1 + c);
        ull a0 = *reinterpret_cast<const ull*>(hsr0 + c);
        ull a1 = *reinterpret_cast<const ull*>(hsr1 + c);
        ull x, v;
        float va, vb;
        x = p2_add(a0, dA[ci]);
        v = p2_fma(p2_fma(x, rsp0, nmp0), gp, bp);
        p2_unpack(v, va, vb);
        af[0][kk][h * 2 + 0] = pack_h2(fmaxf(va, 0.f), fmaxf(vb, 0.f));
        x = p2_add(a0, dB[ci]);
        v = p2_fma(p2_fma(x, rsp1, nmp1), gp, bp);
        p2_unpack(v, va, vb);
        af[0][kk][h * 2 + 1] = pack_h2(fmaxf(va, 0.f), fmaxf(vb, 0.f));
        x = p2_add(a1, dA[ci]);
        v = p2_fma(p2_fma(x, rsp2, nmp2), gp, bp);
        p2_unpack(v, va, vb);
        af[1][kk][h * 2 + 0] = pack_h2(fmaxf(va, 0.f), fmaxf(vb, 0.f));
        x = p2_add(a1, dB[ci]);
        v = p2_fma(p2_fma(x, rsp3, nmp3), gp, bp);
        p2_unpack(v, va, vb);
        af[1][kk][h * 2 + 1] = pack_h2(fmaxf(va, 0.f), fmaxf(vb, 0.f));
    }

    // ---- fused MMA, acc initialized with b2 ----
    float acc[2][8][4];
    #pragma unroll
    for (int nt = 0; nt < 8; nt++) {
        int c = nt * 8 + qc * 2;
        ull b2p = *reinterpret_cast<const ull*>(s_b2 + c);
        float bxv, byv;
        p2_unpack(b2p, bxv, byv);
        #pragma unroll
        for (int mt = 0; mt < 2; mt++) {
            acc[mt][nt][0] = bxv; acc[mt][nt][1] = byv;
            acc[mt][nt][2] = bxv; acc[mt][nt][3] = byv;
        }
    }
    #pragma unroll
    for (int nt = 0; nt < 8; nt++) {
        #pragma unroll
        for (int kk = 0; kk < 4; kk++) {
            uint2 B = s_bf[(nt * 4 + kk) * 32 + lane];
            mma_f16(acc[0][nt], af[0][kk][0], af[0][kk][1], af[0][kk][2], af[0][kk][3], B.x, B.y);
            mma_f16(acc[1][nt], af[1][kk][0], af[1][kk][1], af[1][kk][2], af[1][kk][3], B.x, B.y);
        }
    }

    // ---- Epilogue Phase A: LN2 stats for both mtiles, batched reductions ----
    ull ts[2][2][2];   // [mt][jrow][sum|sq]
    #pragma unroll
    for (int mt = 0; mt < 2; mt++) {
        ull t0 = 0ull, t1 = 0ull, t2 = 0ull, t3 = 0ull;
        #pragma unroll
        for (int nt = 0; nt < 8; nt++) {
            ull ua = p2_pack(acc[mt][nt][0], acc[mt][nt][1]);
            ull ub = p2_pack(acc[mt][nt][2], acc[mt][nt][3]);
            t0 = p2_add(t0, ua); t1 = p2_fma(ua, ua, t1);
            t2 = p2_add(t2, ub); t3 = p2_fma(ub, ub, t3);
        }
        ts[mt][0][0] = t0; ts[mt][0][1] = t1;
        ts[mt][1][0] = t2; ts[mt][1][1] = t3;
    }
    float tr[2][2][2];
    #pragma unroll
    for (int mt = 0; mt < 2; mt++)
        #pragma unroll
        for (int rr = 0; rr < 2; rr++)
            #pragma unroll
            for (int e = 0; e < 2; e++) {
                p2_unpack(ts[mt][rr][e], lo, hi);
                tr[mt][rr][e] = lo + hi;
            }
    #pragma unroll
    for (int mt = 0; mt < 2; mt++)
        #pragma unroll
        for (int rr = 0; rr < 2; rr++)
            #pragma unroll
            for (int e = 0; e < 2; e++)
                tr[mt][rr][e] = qred(tr[mt][rr][e]);     // 8 batched reductions
    ull rp[2][2], np[2][2];
    #pragma unroll
    for (int mt = 0; mt < 2; mt++)
        #pragma unroll
        for (int rr = 0; rr < 2; rr++) {
            float m = tr[mt][rr][0] * (1.f / HH);
            float r = rsqrtf(tr[mt][rr][1] * (1.f / HH) - m * m + LN_EPS);
            rp[mt][rr] = p2_pack(r, r);
            np[mt][rr] = p2_pack(-m * r, -m * r);
        }

    // ---- Epilogue Phase B: nt-outer, params loaded once per column ----
    ull dacc[2][2] = {{0ull, 0ull}, {0ull, 0ull}};
    #pragma unroll
    for (int nt = 0; nt < 8; nt++) {
        int c = nt * 8 + qc * 2;
        ull g2p  = *reinterpret_cast<const ull*>(s_g2 + c);
        ull be2p = *reinterpret_cast<const ull*>(s_be2 + c);
        ull w3p  = *reinterpret_cast<const ull*>(s_w3 + c);
        #pragma unroll
        for (int mt = 0; mt < 2; mt++) {
            float za, zb;
            ull ua = p2_pack(acc[mt][nt][0], acc[mt][nt][1]);
            ull z1 = p2_fma(p2_fma(ua, rp[mt][0], np[mt][0]), g2p, be2p);
            p2_unpack(z1, za, zb);
            dacc[mt][0] = p2_fma(p2_pack(fmaxf(za, 0.f), fmaxf(zb, 0.f)), w3p, dacc[mt][0]);
            ull ub = p2_pack(acc[mt][nt][2], acc[mt][nt][3]);
            ull z2 = p2_fma(p2_fma(ub, rp[mt][1], np[mt][1]), g2p, be2p);
            p2_unpack(z2, za, zb);
            dacc[mt][1] = p2_fma(p2_pack(fmaxf(za, 0.f), fmaxf(zb, 0.f)), w3p, dacc[mt][1]);
        }
    }
    float dv[2][2];
    #pragma unroll
    for (int mt = 0; mt < 2; mt++)
        #pragma unroll
        for (int rr = 0; rr < 2; rr++) {
            p2_unpack(dacc[mt][rr], lo, hi);
            dv[mt][rr] = lo + hi;
        }
    dv[0][0] = qred(dv[0][0]); dv[0][1] = qred(dv[0][1]);
    dv[1][0] = qred(dv[1][0]); dv[1][1] = qred(dv[1][1]);
    if (qc == 0) {
        int j1 = bx * 16 + qr;
        float b3v = s_b3;
        #pragma unroll
        for (int mt = 0; mt < 2; mt++) {
            int i = by * 8 + w * 2 + mt;
            out[i * NN + j1]     = 1.f / (1.f + __expf(-(dv[mt][0] + b3v)));
            out[i * NN + j1 + 8] = 1.f / (1.f + __expf(-(dv[mt][1] + b3v)));
        }
    }
}

// ---------------- launch ----------------
extern "C" void kernel_launch(void* const* d_in, const int* in_sizes, int n_in,
                              void* d_out, int out_size) {
    const float* X   = (const float*)d_in[0];
    const float* W1  = (const float*)d_in[1];
    const float* b1  = (const float*)d_in[2];
    const float* g1  = (const float*)d_in[3];
    const float* be1 = (const float*)d_in[4];
    const float* W2  = (const float*)d_in[5];
    const float* b2  = (const float*)d_in[6];
    const float* g2  = (const float*)d_in[7];
    const float* be2 = (const float*)d_in[8];
    const float* W3  = (const float*)d_in[9];
    const float* b3  = (const float*)d_in[10];
    float* out = (float*)d_out;

    prep_all<<<260, 256>>>(X, W1, b1, W2);
    dim3 grid(NN / 16, NN / 8);
    pair_kernel<<<grid, 128>>>(g1, be1, b2, g2, be2, W3, b3, out);
}

// round 13
// speedup vs baseline: 1.3105x; 1.0142x over previous
#include <cuda_runtime.h>
#include <cuda_fp16.h>
#include <cstdint>

#define NN 1024
#define DD 32
#define HH 64
#define LN_EPS 1e-5f
#define PADH 68   // smem row stride (floats): max 2-way conflicts; 68%4==0 keeps float4 alignment

typedef unsigned long long ull;

// ---------------- device globals ----------------
__device__ float g_hs[NN * HH];        // X @ W1[:32]
__device__ float g_hd[NN * HH];        // X @ W1[32:] + b1
__device__ float g_hsum[NN];           // row sums of g_hs
__device__ float g_dsum[NN];           // row sums of g_hd
__device__ uint4 g_w2f4[8 * 2 * 32];   // fp16 W2 B-frags: [nt][kp][lane] = {kk=2kp: b0,b1 | kk=2kp+1: b0,b1}

// ---------------- packed f32x2 helpers ----------------
__device__ __forceinline__ ull p2_add(ull a, ull b) {
    ull r; asm("add.rn.f32x2 %0, %1, %2;" : "=l"(r) : "l"(a), "l"(b)); return r;
}
__device__ __forceinline__ ull p2_fma(ull a, ull b, ull c) {
    ull r; asm("fma.rn.f32x2 %0, %1, %2, %3;" : "=l"(r) : "l"(a), "l"(b), "l"(c)); return r;
}
__device__ __forceinline__ ull p2_pack(float lo, float hi) {
    ull r; asm("mov.b64 %0, {%1, %2};" : "=l"(r) : "f"(lo), "f"(hi)); return r;
}
__device__ __forceinline__ void p2_unpack(ull v, float& lo, float& hi) {
    asm("mov.b64 {%0, %1}, %2;" : "=f"(lo), "=f"(hi) : "l"(v));
}
__device__ __forceinline__ uint32_t pack_h2(float a, float b) {
    __half2 t = __floats2half2_rn(a, b);
    return *reinterpret_cast<uint32_t*>(&t);
}
__device__ __forceinline__ void mma_f16(float* c, uint32_t a0, uint32_t a1,
                                        uint32_t a2, uint32_t a3,
                                        uint32_t b0, uint32_t b1) {
    asm volatile(
        "mma.sync.aligned.m16n8k16.row.col.f32.f16.f16.f32 "
        "{%0,%1,%2,%3}, {%4,%5,%6,%7}, {%8,%9}, {%0,%1,%2,%3};"
        : "+f"(c[0]), "+f"(c[1]), "+f"(c[2]), "+f"(c[3])
        : "r"(a0), "r"(a1), "r"(a2), "r"(a3), "r"(b0), "r"(b1));
}
__device__ __forceinline__ float qred(float v) {
    v += __shfl_xor_sync(0xffffffffu, v, 1);
    v += __shfl_xor_sync(0xffffffffu, v, 2);
    return v;
}
__device__ __forceinline__ float wred32(float v) {
    #pragma unroll
    for (int s = 16; s > 0; s >>= 1) v += __shfl_xor_sync(0xffffffffu, v, s);
    return v;
}

// ---------------- merged prep (single-sync reductions) ----------------
__global__ void prep_all(const float* __restrict__ X,
                         const float* __restrict__ W1,
                         const float* __restrict__ b1,
                         const float* __restrict__ W2) {
    if (blockIdx.x < 256) {
        __shared__ float xs[4][DD];
        __shared__ float redh[4][HH];
        __shared__ float redd[4][HH];
        int sub = threadIdx.x >> 6;
        int n = threadIdx.x & 63;
        int i = blockIdx.x * 4 + sub;
        if (n < DD) xs[sub][n] = X[i * DD + n];
        __syncthreads();
        float hs = 0.f, hd = b1[n];
        #pragma unroll
        for (int d = 0; d < DD; d++) {
            float xv = xs[sub][d];
            hs = fmaf(xv, W1[d * HH + n], hs);
            hd = fmaf(xv, W1[(DD + d) * HH + n], hd);
        }
        g_hs[i * HH + n] = hs;
        g_hd[i * HH + n] = hd;
        redh[sub][n] = hs;
        redd[sub][n] = hd;
        __syncthreads();
        // 8 warps handle 8 reductions concurrently: warps 0-3 -> hs[sub], 4-7 -> hd[sub]
        int wi = threadIdx.x >> 5, lid = threadIdx.x & 31;
        int s2 = wi & 3;
        const float* src = (wi >= 4) ? redd[s2] : redh[s2];
        float v = src[lid] + src[lid + 32];
        v = wred32(v);
        if (lid == 0) {
            if (wi >= 4) g_dsum[blockIdx.x * 4 + s2] = v;
            else         g_hsum[blockIdx.x * 4 + s2] = v;
        }
    } else {
        // W2 -> uint4 B-frags: (nt, kp, lane); 512 entries, 256 threads x 2
        #pragma unroll
        for (int e = 0; e < 2; e++) {
            int tt = threadIdx.x + e * 256;
            int lane = tt & 31;
            int kp = (tt >> 5) & 1;
            int nt = tt >> 6;
            int n  = nt * 8 + (lane >> 2);
            int kq = kp * 32 + (lane & 3) * 2;
            uint4 r;
            r.x = pack_h2(W2[kq * HH + n],        W2[(kq + 1) * HH + n]);
            r.y = pack_h2(W2[(kq + 8) * HH + n],  W2[(kq + 9) * HH + n]);
            r.z = pack_h2(W2[(kq + 16) * HH + n], W2[(kq + 17) * HH + n]);
            r.w = pack_h2(W2[(kq + 24) * HH + n], W2[(kq + 25) * HH + n]);
            g_w2f4[tt] = r;
        }
    }
}

// ---------------- main pair kernel ----------------
__global__ __launch_bounds__(128, 4) void pair_kernel(
    const float* __restrict__ g1, const float* __restrict__ be1,
    const float* __restrict__ b2, const float* __restrict__ g2,
    const float* __restrict__ be2, const float* __restrict__ W3,
    const float* __restrict__ b3, float* __restrict__ out) {
    __shared__ uint4 s_bf4[8 * 2 * 32];
    __shared__ __align__(16) float s_hd[16 * PADH];
    __shared__ __align__(16) float s_hs[8 * PADH];
    __shared__ __align__(8) float s_g1[HH];
    __shared__ __align__(8) float s_be1[HH];
    __shared__ __align__(8) float s_b2[HH];
    __shared__ __align__(8) float s_g2[HH];
    __shared__ __align__(8) float s_be2[HH];
    __shared__ __align__(8) float s_w3[HH];
    __shared__ float s_S[8], s_T[16], s_b3;

    int tid = threadIdx.x;
    int w = tid >> 5, lane = tid & 31;
    int qr = lane >> 2, qc = lane & 3;
    int bx = blockIdx.x, by = blockIdx.y;

    // ---- vectorized staging ----
    #pragma unroll
    for (int idx = tid; idx < 512; idx += 128) s_bf4[idx] = g_w2f4[idx];
    #pragma unroll
    for (int e = 0; e < 2; e++) {
        int idx = tid + e * 128;              // 256 float4 = 16 rows x 16
        int r = idx >> 4, c4 = idx & 15;
        float4 v = *reinterpret_cast<const float4*>(g_hd + (bx * 16 + r) * HH + c4 * 4);
        *reinterpret_cast<float4*>(s_hd + r * PADH + c4 * 4) = v;
    }
    {
        int r = tid >> 4, c4 = tid & 15;      // 128 float4 = 8 rows x 16
        float4 v = *reinterpret_cast<const float4*>(g_hs + (by * 8 + r) * HH + c4 * 4);
        *reinterpret_cast<float4*>(s_hs + r * PADH + c4 * 4) = v;
    }
    if (tid < HH) {
        s_g1[tid]  = g1[tid];
        s_be1[tid] = be1[tid];
        s_b2[tid]  = b2[tid];
        s_g2[tid]  = g2[tid];
        s_be2[tid] = be2[tid];
        s_w3[tid]  = W3[tid];
    }
    if (tid < 8)  s_S[tid] = g_hsum[by * 8 + tid];
    if (tid < 16) s_T[tid] = g_dsum[bx * 16 + tid];
    if (tid == 0) s_b3 = b3[0];
    __syncthreads();

    // ---- hd rows in registers (reused across all 4 combos) ----
    const float* hdr1 = s_hd + qr * PADH;
    const float* hdr2 = s_hd + (qr + 8) * PADH;
    ull dA[8], dB[8];
    #pragma unroll
    for (int ci = 0; ci < 8; ci++) {
        int c = (ci >> 1) * 16 + (ci & 1) * 8 + qc * 2;
        dA[ci] = *reinterpret_cast<const ull*>(hdr1 + c);
        dB[ci] = *reinterpret_cast<const ull*>(hdr2 + c);
    }
    const float* hsr0 = s_hs + (w * 2) * PADH;
    const float* hsr1 = s_hs + (w * 2 + 1) * PADH;

    // ---- Phase A: four independent packed sum-of-squares, batched reductions ----
    ull s2p0 = 0ull, s2p1 = 0ull, s2p2 = 0ull, s2p3 = 0ull;
    #pragma unroll
    for (int ci = 0; ci < 8; ci++) {
        int c = (ci >> 1) * 16 + (ci & 1) * 8 + qc * 2;
        ull a0 = *reinterpret_cast<const ull*>(hsr0 + c);   // quad-broadcast
        ull a1 = *reinterpret_cast<const ull*>(hsr1 + c);
        ull x;
        x = p2_add(a0, dA[ci]); s2p0 = p2_fma(x, x, s2p0);
        x = p2_add(a0, dB[ci]); s2p1 = p2_fma(x, x, s2p1);
        x = p2_add(a1, dA[ci]); s2p2 = p2_fma(x, x, s2p2);
        x = p2_add(a1, dB[ci]); s2p3 = p2_fma(x, x, s2p3);
    }
    float lo, hi;
    p2_unpack(s2p0, lo, hi); float q0 = lo + hi;
    p2_unpack(s2p1, lo, hi); float q1 = lo + hi;
    p2_unpack(s2p2, lo, hi); float q2 = lo + hi;
    p2_unpack(s2p3, lo, hi); float q3 = lo + hi;
    q0 = qred(q0); q1 = qred(q1); q2 = qred(q2); q3 = qred(q3);   // ILP-batched
    float Sv0 = s_S[w * 2], Sv1 = s_S[w * 2 + 1];
    float Tv1 = s_T[qr],    Tv2 = s_T[qr + 8];
    float mu0 = (Sv0 + Tv1) * (1.f / HH);
    float mu1 = (Sv0 + Tv2) * (1.f / HH);
    float mu2 = (Sv1 + Tv1) * (1.f / HH);
    float mu3 = (Sv1 + Tv2) * (1.f / HH);
    float rs0 = rsqrtf(q0 * (1.f / HH) - mu0 * mu0 + LN_EPS);
    float rs1 = rsqrtf(q1 * (1.f / HH) - mu1 * mu1 + LN_EPS);
    float rs2 = rsqrtf(q2 * (1.f / HH) - mu2 * mu2 + LN_EPS);
    float rs3 = rsqrtf(q3 * (1.f / HH) - mu3 * mu3 + LN_EPS);
    ull rsp0 = p2_pack(rs0, rs0), nmp0 = p2_pack(-mu0 * rs0, -mu0 * rs0);
    ull rsp1 = p2_pack(rs1, rs1), nmp1 = p2_pack(-mu1 * rs1, -mu1 * rs1);
    ull rsp2 = p2_pack(rs2, rs2), nmp2 = p2_pack(-mu2 * rs2, -mu2 * rs2);
    ull rsp3 = p2_pack(rs3, rs3), nmp3 = p2_pack(-mu3 * rs3, -mu3 * rs3);

    // ---- Phase B: apply, column-outer so gp/bp are loaded ONCE per column ----
    uint32_t af[2][4][4];
    #pragma unroll
    for (int ci = 0; ci < 8; ci++) {
        int kk = ci >> 1, h = ci & 1;
        int c = kk * 16 + h * 8 + qc * 2;
        ull gp = *reinterpret_cast<const ull*>(s_g1 + c);
        ull bp = *reinterpret_cast<const ull*>(s_be1 + c);
        ull a0 = *reinterpret_cast<const ull*>(hsr0 + c);
        ull a1 = *reinterpret_cast<const ull*>(hsr1 + c);
        ull x, v;
        float va, vb;
        x = p2_add(a0, dA[ci]);
        v = p2_fma(p2_fma(x, rsp0, nmp0), gp, bp);
        p2_unpack(v, va, vb);
        af[0][kk][h * 2 + 0] = pack_h2(fmaxf(va, 0.f), fmaxf(vb, 0.f));
        x = p2_add(a0, dB[ci]);
        v = p2_fma(p2_fma(x, rsp1, nmp1), gp, bp);
        p2_unpack(v, va, vb);
        af[0][kk][h * 2 + 1] = pack_h2(fmaxf(va, 0.f), fmaxf(vb, 0.f));
        x = p2_add(a1, dA[ci]);
        v = p2_fma(p2_fma(x, rsp2, nmp2), gp, bp);
        p2_unpack(v, va, vb);
        af[1][kk][h * 2 + 0] = pack_h2(fmaxf(va, 0.f), fmaxf(vb, 0.f));
        x = p2_add(a1, dB[ci]);
        v = p2_fma(p2_fma(x, rsp3, nmp3), gp, bp);
        p2_unpack(v, va, vb);
        af[1][kk][h * 2 + 1] = pack_h2(fmaxf(va, 0.f), fmaxf(vb, 0.f));
    }

    // ---- fused MMA, acc initialized with b2; uint4 B-frags (half the LDS issues) ----
    float acc[2][8][4];
    #pragma unroll
    for (int nt = 0; nt < 8; nt++) {
        int c = nt * 8 + qc * 2;
        ull b2p = *reinterpret_cast<const ull*>(s_b2 + c);
        float bxv, byv;
        p2_unpack(b2p, bxv, byv);
        #pragma unroll
        for (int mt = 0; mt < 2; mt++) {
            acc[mt][nt][0] = bxv; acc[mt][nt][1] = byv;
            acc[mt][nt][2] = bxv; acc[mt][nt][3] = byv;
        }
    }
    #pragma unroll
    for (int nt = 0; nt < 8; nt++) {
        #pragma unroll
        for (int kp = 0; kp < 2; kp++) {
            uint4 B = s_bf4[(nt * 2 + kp) * 32 + lane];
            int k0 = 2 * kp, k1 = 2 * kp + 1;
            mma_f16(acc[0][nt], af[0][k0][0], af[0][k0][1], af[0][k0][2], af[0][k0][3], B.x, B.y);
            mma_f16(acc[1][nt], af[1][k0][0], af[1][k0][1], af[1][k0][2], af[1][k0][3], B.x, B.y);
            mma_f16(acc[0][nt], af[0][k1][0], af[0][k1][1], af[0][k1][2], af[0][k1][3], B.z, B.w);
            mma_f16(acc[1][nt], af[1][k1][0], af[1][k1][1], af[1][k1][2], af[1][k1][3], B.z, B.w);
        }
    }

    // ---- Epilogue Phase A: LN2 stats for both mtiles, batched reductions ----
    ull ts[2][2][2];   // [mt][jrow][sum|sq]
    #pragma unroll
    for (int mt = 0; mt < 2; mt++) {
        ull t0 = 0ull, t1 = 0ull, t2 = 0ull, t3 = 0ull;
        #pragma unroll
        for (int nt = 0; nt < 8; nt++) {
            ull ua = p2_pack(acc[mt][nt][0], acc[mt][nt][1]);
            ull ub = p2_pack(acc[mt][nt][2], acc[mt][nt][3]);
            t0 = p2_add(t0, ua); t1 = p2_fma(ua, ua, t1);
            t2 = p2_add(t2, ub); t3 = p2_fma(ub, ub, t3);
        }
        ts[mt][0][0] = t0; ts[mt][0][1] = t1;
        ts[mt][1][0] = t2; ts[mt][1][1] = t3;
    }
    float tr[2][2][2];
    #pragma unroll
    for (int mt = 0; mt < 2; mt++)
        #pragma unroll
        for (int rr = 0; rr < 2; rr++)
            #pragma unroll
            for (int e = 0; e < 2; e++) {
                p2_unpack(ts[mt][rr][e], lo, hi);
                tr[mt][rr][e] = lo + hi;
            }
    #pragma unroll
    for (int mt = 0; mt < 2; mt++)
        #pragma unroll
        for (int rr = 0; rr < 2; rr++)
            #pragma unroll
            for (int e = 0; e < 2; e++)
                tr[mt][rr][e] = qred(tr[mt][rr][e]);     // 8 batched reductions
    ull rp[2][2], np[2][2];
    #pragma unroll
    for (int mt = 0; mt < 2; mt++)
        #pragma unroll
        for (int rr = 0; rr < 2; rr++) {
            float m = tr[mt][rr][0] * (1.f / HH);
            float r = rsqrtf(tr[mt][rr][1] * (1.f / HH) - m * m + LN_EPS);
            rp[mt][rr] = p2_pack(r, r);
            np[mt][rr] = p2_pack(-m * r, -m * r);
        }

    // ---- Epilogue Phase B: nt-outer, params loaded once per column ----
    ull dacc[2][2] = {{0ull, 0ull}, {0ull, 0ull}};
    #pragma unroll
    for (int nt = 0; nt < 8; nt++) {
        int c = nt * 8 + qc * 2;
        ull g2p  = *reinterpret_cast<const ull*>(s_g2 + c);
        ull be2p = *reinterpret_cast<const ull*>(s_be2 + c);
        ull w3p  = *reinterpret_cast<const ull*>(s_w3 + c);
        #pragma unroll
        for (int mt = 0; mt < 2; mt++) {
            float za, zb;
            ull ua = p2_pack(acc[mt][nt][0], acc[mt][nt][1]);
            ull z1 = p2_fma(p2_fma(ua, rp[mt][0], np[mt][0]), g2p, be2p);
            p2_unpack(z1, za, zb);
            dacc[mt][0] = p2_fma(p2_pack(fmaxf(za, 0.f), fmaxf(zb, 0.f)), w3p, dacc[mt][0]);
            ull ub = p2_pack(acc[mt][nt][2], acc[mt][nt][3]);
            ull z2 = p2_fma(p2_fma(ub, rp[mt][1], np[mt][1]), g2p, be2p);
            p2_unpack(z2, za, zb);
            dacc[mt][1] = p2_fma(p2_pack(fmaxf(za, 0.f), fmaxf(zb, 0.f)), w3p, dacc[mt][1]);
        }
    }
    float dv[2][2];
    #pragma unroll
    for (int mt = 0; mt < 2; mt++)
        #pragma unroll
        for (int rr = 0; rr < 2; rr++) {
            p2_unpack(dacc[mt][rr], lo, hi);
            dv[mt][rr] = lo + hi;
        }
    dv[0][0] = qred(dv[0][0]); dv[0][1] = qred(dv[0][1]);
    dv[1][0] = qred(dv[1][0]); dv[1][1] = qred(dv[1][1]);
    if (qc == 0) {
        int j1 = bx * 16 + qr;
        float b3v = s_b3;
        #pragma unroll
        for (int mt = 0; mt < 2; mt++) {
            int i = by * 8 + w * 2 + mt;
            out[i * NN + j1]     = 1.f / (1.f + __expf(-(dv[mt][0] + b3v)));
            out[i * NN + j1 + 8] = 1.f / (1.f + __expf(-(dv[mt][1] + b3v)));
        }
    }
}

// ---------------- launch ----------------
extern "C" void kernel_launch(void* const* d_in, const int* in_sizes, int n_in,
                              void* d_out, int out_size) {
    const float* X   = (const float*)d_in[0];
    const float* W1  = (const float*)d_in[1];
    const float* b1  = (const float*)d_in[2];
    const float* g1  = (const float*)d_in[3];
    const float* be1 = (const float*)d_in[4];
    const float* W2  = (const float*)d_in[5];
    const float* b2  = (const float*)d_in[6];
    const float* g2  = (const float*)d_in[7];
    const float* be2 = (const float*)d_in[8];
    const float* W3  = (const float*)d_in[9];
    const float* b3  = (const float*)d_in[10];
    float* out = (float*)d_out;

    prep_all<<<257, 256>>>(X, W1, b1, W2);
    dim3 grid(NN / 16, NN / 8);
    pair_kernel<<<grid, 128>>>(g1, be1, b2, g2, be2, W3, b3, out);
}

// round 14
// speedup vs baseline: 1.3342x; 1.0181x over previous
#include <cuda_runtime.h>
#include <cuda_fp16.h>
#include <cstdint>

#define NN 1024
#define DD 32
#define HH 64
#define LN_EPS 1e-5f

typedef unsigned long long ull;

// ---------------- device globals ----------------
__device__ float g_hs[NN * HH];        // X @ W1[:32]
__device__ float g_hd[NN * HH];        // X @ W1[32:] + b1
__device__ float g_hsum[NN];           // row sums of g_hs
__device__ float g_dsum[NN];           // row sums of g_hd
__device__ uint4 g_w2f4[8 * 2 * 32];   // fp16 W2 B-frags: [nt][kp][lane]

// ---------------- packed f32x2 helpers ----------------
__device__ __forceinline__ ull p2_add(ull a, ull b) {
    ull r; asm("add.rn.f32x2 %0, %1, %2;" : "=l"(r) : "l"(a), "l"(b)); return r;
}
__device__ __forceinline__ ull p2_fma(ull a, ull b, ull c) {
    ull r; asm("fma.rn.f32x2 %0, %1, %2, %3;" : "=l"(r) : "l"(a), "l"(b), "l"(c)); return r;
}
__device__ __forceinline__ ull p2_pack(float lo, float hi) {
    ull r; asm("mov.b64 %0, {%1, %2};" : "=l"(r) : "f"(lo), "f"(hi)); return r;
}
__device__ __forceinline__ void p2_unpack(ull v, float& lo, float& hi) {
    asm("mov.b64 {%0, %1}, %2;" : "=f"(lo), "=f"(hi) : "l"(v));
}
__device__ __forceinline__ uint32_t pack_h2(float a, float b) {
    __half2 t = __floats2half2_rn(a, b);
    return *reinterpret_cast<uint32_t*>(&t);
}
__device__ __forceinline__ void mma_f16(float* c, uint32_t a0, uint32_t a1,
                                        uint32_t a2, uint32_t a3,
                                        uint32_t b0, uint32_t b1) {
    asm volatile(
        "mma.sync.aligned.m16n8k16.row.col.f32.f16.f16.f32 "
        "{%0,%1,%2,%3}, {%4,%5,%6,%7}, {%8,%9}, {%0,%1,%2,%3};"
        : "+f"(c[0]), "+f"(c[1]), "+f"(c[2]), "+f"(c[3])
        : "r"(a0), "r"(a1), "r"(a2), "r"(a3), "r"(b0), "r"(b1));
}
__device__ __forceinline__ float qred(float v) {
    v += __shfl_xor_sync(0xffffffffu, v, 1);
    v += __shfl_xor_sync(0xffffffffu, v, 2);
    return v;
}
__device__ __forceinline__ float wred32(float v) {
    #pragma unroll
    for (int s = 16; s > 0; s >>= 1) v += __shfl_xor_sync(0xffffffffu, v, s);
    return v;
}
__device__ __forceinline__ ull ldg_ull(const float* p) {
    return *reinterpret_cast<const ull*>(p);
}

// ---------------- merged prep (single-sync reductions) ----------------
__global__ void prep_all(const float* __restrict__ X,
                         const float* __restrict__ W1,
                         const float* __restrict__ b1,
                         const float* __restrict__ W2) {
    if (blockIdx.x < 256) {
        __shared__ float xs[4][DD];
        __shared__ float redh[4][HH];
        __shared__ float redd[4][HH];
        int sub = threadIdx.x >> 6;
        int n = threadIdx.x & 63;
        int i = blockIdx.x * 4 + sub;
        if (n < DD) xs[sub][n] = X[i * DD + n];
        __syncthreads();
        float hs = 0.f, hd = b1[n];
        #pragma unroll
        for (int d = 0; d < DD; d++) {
            float xv = xs[sub][d];
            hs = fmaf(xv, W1[d * HH + n], hs);
            hd = fmaf(xv, W1[(DD + d) * HH + n], hd);
        }
        g_hs[i * HH + n] = hs;
        g_hd[i * HH + n] = hd;
        redh[sub][n] = hs;
        redd[sub][n] = hd;
        __syncthreads();
        int wi = threadIdx.x >> 5, lid = threadIdx.x & 31;
        int s2 = wi & 3;
        const float* src = (wi >= 4) ? redd[s2] : redh[s2];
        float v = src[lid] + src[lid + 32];
        v = wred32(v);
        if (lid == 0) {
            if (wi >= 4) g_dsum[blockIdx.x * 4 + s2] = v;
            else         g_hsum[blockIdx.x * 4 + s2] = v;
        }
    } else {
        #pragma unroll
        for (int e = 0; e < 2; e++) {
            int tt = threadIdx.x + e * 256;
            int lane = tt & 31;
            int kp = (tt >> 5) & 1;
            int nt = tt >> 6;
            int n  = nt * 8 + (lane >> 2);
            int kq = kp * 32 + (lane & 3) * 2;
            uint4 r;
            r.x = pack_h2(W2[kq * HH + n],        W2[(kq + 1) * HH + n]);
            r.y = pack_h2(W2[(kq + 8) * HH + n],  W2[(kq + 9) * HH + n]);
            r.z = pack_h2(W2[(kq + 16) * HH + n], W2[(kq + 17) * HH + n]);
            r.w = pack_h2(W2[(kq + 24) * HH + n], W2[(kq + 25) * HH + n]);
            g_w2f4[tt] = r;
        }
    }
}

// ---------------- main pair kernel: zero smem, zero sync, all reads via L1 ----------------
__global__ __launch_bounds__(128, 4) void pair_kernel(
    const float* __restrict__ g1, const float* __restrict__ be1,
    const float* __restrict__ b2, const float* __restrict__ g2,
    const float* __restrict__ be2, const float* __restrict__ W3,
    const float* __restrict__ b3, float* __restrict__ out) {
    int tid = threadIdx.x;
    int w = tid >> 5, lane = tid & 31;
    int qr = lane >> 2, qc = lane & 3;
    int bx = blockIdx.x, by = blockIdx.y;

    // ---- hd rows in registers (L1-hot: shared across co-resident CTAs) ----
    const float* hdr1 = g_hd + (bx * 16 + qr) * HH;
    const float* hdr2 = g_hd + (bx * 16 + qr + 8) * HH;
    ull dA[8], dB[8];
    #pragma unroll
    for (int ci = 0; ci < 8; ci++) {
        int c = (ci >> 1) * 16 + (ci & 1) * 8 + qc * 2;
        dA[ci] = ldg_ull(hdr1 + c);
        dB[ci] = ldg_ull(hdr2 + c);
    }
    const float* hsr0 = g_hs + (by * 8 + w * 2) * HH;
    const float* hsr1 = hsr0 + HH;

    // ---- Phase A: four independent packed sum-of-squares, batched reductions ----
    ull s2p0 = 0ull, s2p1 = 0ull, s2p2 = 0ull, s2p3 = 0ull;
    #pragma unroll
    for (int ci = 0; ci < 8; ci++) {
        int c = (ci >> 1) * 16 + (ci & 1) * 8 + qc * 2;
        ull a0 = ldg_ull(hsr0 + c);
        ull a1 = ldg_ull(hsr1 + c);
        ull x;
        x = p2_add(a0, dA[ci]); s2p0 = p2_fma(x, x, s2p0);
        x = p2_add(a0, dB[ci]); s2p1 = p2_fma(x, x, s2p1);
        x = p2_add(a1, dA[ci]); s2p2 = p2_fma(x, x, s2p2);
        x = p2_add(a1, dB[ci]); s2p3 = p2_fma(x, x, s2p3);
    }
    float lo, hi;
    p2_unpack(s2p0, lo, hi); float q0 = lo + hi;
    p2_unpack(s2p1, lo, hi); float q1 = lo + hi;
    p2_unpack(s2p2, lo, hi); float q2 = lo + hi;
    p2_unpack(s2p3, lo, hi); float q3 = lo + hi;
    q0 = qred(q0); q1 = qred(q1); q2 = qred(q2); q3 = qred(q3);
    float Sv0 = g_hsum[by * 8 + w * 2], Sv1 = g_hsum[by * 8 + w * 2 + 1];
    float Tv1 = g_dsum[bx * 16 + qr],   Tv2 = g_dsum[bx * 16 + qr + 8];
    float mu0 = (Sv0 + Tv1) * (1.f / HH);
    float mu1 = (Sv0 + Tv2) * (1.f / HH);
    float mu2 = (Sv1 + Tv1) * (1.f / HH);
    float mu3 = (Sv1 + Tv2) * (1.f / HH);
    float rs0 = rsqrtf(q0 * (1.f / HH) - mu0 * mu0 + LN_EPS);
    float rs1 = rsqrtf(q1 * (1.f / HH) - mu1 * mu1 + LN_EPS);
    float rs2 = rsqrtf(q2 * (1.f / HH) - mu2 * mu2 + LN_EPS);
    float rs3 = rsqrtf(q3 * (1.f / HH) - mu3 * mu3 + LN_EPS);
    ull rsp0 = p2_pack(rs0, rs0), nmp0 = p2_pack(-mu0 * rs0, -mu0 * rs0);
    ull rsp1 = p2_pack(rs1, rs1), nmp1 = p2_pack(-mu1 * rs1, -mu1 * rs1);
    ull rsp2 = p2_pack(rs2, rs2), nmp2 = p2_pack(-mu2 * rs2, -mu2 * rs2);
    ull rsp3 = p2_pack(rs3, rs3), nmp3 = p2_pack(-mu3 * rs3, -mu3 * rs3);

    // ---- Phase B: apply, column-outer (params loaded once per column, L1-hit) ----
    uint32_t af[2][4][4];
    #pragma unroll
    for (int ci = 0; ci < 8; ci++) {
        int kk = ci >> 1, h = ci & 1;
        int c = kk * 16 + h * 8 + qc * 2;
        ull gp = ldg_ull(g1 + c);
        ull bp = ldg_ull(be1 + c);
        ull a0 = ldg_ull(hsr0 + c);
        ull a1 = ldg_ull(hsr1 + c);
        ull x, v;
        float va, vb;
        x = p2_add(a0, dA[ci]);
        v = p2_fma(p2_fma(x, rsp0, nmp0), gp, bp);
        p2_unpack(v, va, vb);
        af[0][kk][h * 2 + 0] = pack_h2(fmaxf(va, 0.f), fmaxf(vb, 0.f));
        x = p2_add(a0, dB[ci]);
        v = p2_fma(p2_fma(x, rsp1, nmp1), gp, bp);
        p2_unpack(v, va, vb);
        af[0][kk][h * 2 + 1] = pack_h2(fmaxf(va, 0.f), fmaxf(vb, 0.f));
        x = p2_add(a1, dA[ci]);
        v = p2_fma(p2_fma(x, rsp2, nmp2), gp, bp);
        p2_unpack(v, va, vb);
        af[1][kk][h * 2 + 0] = pack_h2(fmaxf(va, 0.f), fmaxf(vb, 0.f));
        x = p2_add(a1, dB[ci]);
        v = p2_fma(p2_fma(x, rsp3, nmp3), gp, bp);
        p2_unpack(v, va, vb);
        af[1][kk][h * 2 + 1] = pack_h2(fmaxf(va, 0.f), fmaxf(vb, 0.f));
    }

    // ---- fused MMA, acc initialized with b2; B-frags direct LDG.128 (L1-hot) ----
    float acc[2][8][4];
    #pragma unroll
    for (int nt = 0; nt < 8; nt++) {
        int c = nt * 8 + qc * 2;
        ull b2p = ldg_ull(b2 + c);
        float bxv, byv;
        p2_unpack(b2p, bxv, byv);
        #pragma unroll
        for (int mt = 0; mt < 2; mt++) {
            acc[mt][nt][0] = bxv; acc[mt][nt][1] = byv;
            acc[mt][nt][2] = bxv; acc[mt][nt][3] = byv;
        }
    }
    #pragma unroll
    for (int nt = 0; nt < 8; nt++) {
        #pragma unroll
        for (int kp = 0; kp < 2; kp++) {
            uint4 B = g_w2f4[(nt * 2 + kp) * 32 + lane];
            int k0 = 2 * kp, k1 = 2 * kp + 1;
            mma_f16(acc[0][nt], af[0][k0][0], af[0][k0][1], af[0][k0][2], af[0][k0][3], B.x, B.y);
            mma_f16(acc[1][nt], af[1][k0][0], af[1][k0][1], af[1][k0][2], af[1][k0][3], B.x, B.y);
            mma_f16(acc[0][nt], af[0][k1][0], af[0][k1][1], af[0][k1][2], af[0][k1][3], B.z, B.w);
            mma_f16(acc[1][nt], af[1][k1][0], af[1][k1][1], af[1][k1][2], af[1][k1][3], B.z, B.w);
        }
    }

    // ---- Epilogue Phase A: LN2 stats for both mtiles, batched reductions ----
    ull ts[2][2][2];
    #pragma unroll
    for (int mt = 0; mt < 2; mt++) {
        ull t0 = 0ull, t1 = 0ull, t2 = 0ull, t3 = 0ull;
        #pragma unroll
        for (int nt = 0; nt < 8; nt++) {
            ull ua = p2_pack(acc[mt][nt][0], acc[mt][nt][1]);
            ull ub = p2_pack(acc[mt][nt][2], acc[mt][nt][3]);
            t0 = p2_add(t0, ua); t1 = p2_fma(ua, ua, t1);
            t2 = p2_add(t2, ub); t3 = p2_fma(ub, ub, t3);
        }
        ts[mt][0][0] = t0; ts[mt][0][1] = t1;
        ts[mt][1][0] = t2; ts[mt][1][1] = t3;
    }
    float tr[2][2][2];
    #pragma unroll
    for (int mt = 0; mt < 2; mt++)
        #pragma unroll
        for (int rr = 0; rr < 2; rr++)
            #pragma unroll
            for (int e = 0; e < 2; e++) {
                p2_unpack(ts[mt][rr][e], lo, hi);
                tr[mt][rr][e] = lo + hi;
            }
    #pragma unroll
    for (int mt = 0; mt < 2; mt++)
        #pragma unroll
        for (int rr = 0; rr < 2; rr++)
            #pragma unroll
            for (int e = 0; e < 2; e++)
                tr[mt][rr][e] = qred(tr[mt][rr][e]);
    ull rp[2][2], np[2][2];
    #pragma unroll
    for (int mt = 0; mt < 2; mt++)
        #pragma unroll
        for (int rr = 0; rr < 2; rr++) {
            float m = tr[mt][rr][0] * (1.f / HH);
            float r = rsqrtf(tr[mt][rr][1] * (1.f / HH) - m * m + LN_EPS);
            rp[mt][rr] = p2_pack(r, r);
            np[mt][rr] = p2_pack(-m * r, -m * r);
        }

    // ---- Epilogue Phase B: nt-outer, params loaded once per column ----
    ull dacc[2][2] = {{0ull, 0ull}, {0ull, 0ull}};
    #pragma unroll
    for (int nt = 0; nt < 8; nt++) {
        int c = nt * 8 + qc * 2;
        ull g2p  = ldg_ull(g2 + c);
        ull be2p = ldg_ull(be2 + c);
        ull w3p  = ldg_ull(W3 + c);
        #pragma unroll
        for (int mt = 0; mt < 2; mt++) {
            float za, zb;
            ull ua = p2_pack(acc[mt][nt][0], acc[mt][nt][1]);
            ull z1 = p2_fma(p2_fma(ua, rp[mt][0], np[mt][0]), g2p, be2p);
            p2_unpack(z1, za, zb);
            dacc[mt][0] = p2_fma(p2_pack(fmaxf(za, 0.f), fmaxf(zb, 0.f)), w3p, dacc[mt][0]);
            ull ub = p2_pack(acc[mt][nt][2], acc[mt][nt][3]);
            ull z2 = p2_fma(p2_fma(ub, rp[mt][1], np[mt][1]), g2p, be2p);
            p2_unpack(z2, za, zb);
            dacc[mt][1] = p2_fma(p2_pack(fmaxf(za, 0.f), fmaxf(zb, 0.f)), w3p, dacc[mt][1]);
        }
    }
    float dv[2][2];
    #pragma unroll
    for (int mt = 0; mt < 2; mt++)
        #pragma unroll
        for (int rr = 0; rr < 2; rr++) {
            p2_unpack(dacc[mt][rr], lo, hi);
            dv[mt][rr] = lo + hi;
        }
    dv[0][0] = qred(dv[0][0]); dv[0][1] = qred(dv[0][1]);
    dv[1][0] = qred(dv[1][0]); dv[1][1] = qred(dv[1][1]);
    if (qc == 0) {
        int j1 = bx * 16 + qr;
        float b3v = b3[0];
        #pragma unroll
        for (int mt = 0; mt < 2; mt++) {
            int i = by * 8 + w * 2 + mt;
            out[i * NN + j1]     = 1.f / (1.f + __expf(-(dv[mt][0] + b3v)));
            out[i * NN + j1 + 8] = 1.f / (1.f + __expf(-(dv[mt][1] + b3v)));
        }
    }
}

// ---------------- launch ----------------
extern "C" void kernel_launch(void* const* d_in, const int* in_sizes, int n_in,
                              void* d_out, int out_size) {
    const float* X   = (const float*)d_in[0];
    const float* W1  = (const float*)d_in[1];
    const float* b1  = (const float*)d_in[2];
    const float* g1  = (const float*)d_in[3];
    const float* be1 = (const float*)d_in[4];
    const float* W2  = (const float*)d_in[5];
    const float* b2  = (const float*)d_in[6];
    const float* g2  = (const float*)d_in[7];
    const float* be2 = (const float*)d_in[8];
    const float* W3  = (const float*)d_in[9];
    const float* b3  = (const float*)d_in[10];
    float* out = (float*)d_out;

    prep_all<<<257, 256>>>(X, W1, b1, W2);
    dim3 grid(NN / 16, NN / 8);
    pair_kernel<<<grid, 128>>>(g1, be1, b2, g2, be2, W3, b3, out);
}

// round 15
// speedup vs baseline: 1.4000x; 1.0493x over previous
#include <cuda_runtime.h>
#include <cuda_fp16.h>
#include <cstdint>

#define NN 1024
#define DD 32
#define HH 64
#define LN_EPS 1e-5f

typedef unsigned long long ull;

// ---------------- device globals ----------------
__device__ float g_hs[NN * HH];        // X @ W1[:32]
__device__ float g_hd[NN * HH];        // X @ W1[32:] + b1
__device__ float g_hsum[NN];           // row sums of g_hs
__device__ float g_dsum[NN];           // row sums of g_hd
__device__ uint4 g_w2f4[8 * 2 * 32];   // fp16 W2 B-frags: [nt][kp][lane]
__device__ ull   g_hdF[64 * 2 * 8 * 32]; // hd in pair-kernel fragment order: [blk][rr][ci][lane]

// ---------------- packed f32x2 helpers ----------------
__device__ __forceinline__ ull p2_add(ull a, ull b) {
    ull r; asm("add.rn.f32x2 %0, %1, %2;" : "=l"(r) : "l"(a), "l"(b)); return r;
}
__device__ __forceinline__ ull p2_fma(ull a, ull b, ull c) {
    ull r; asm("fma.rn.f32x2 %0, %1, %2, %3;" : "=l"(r) : "l"(a), "l"(b), "l"(c)); return r;
}
__device__ __forceinline__ ull p2_pack(float lo, float hi) {
    ull r; asm("mov.b64 %0, {%1, %2};" : "=l"(r) : "f"(lo), "f"(hi)); return r;
}
__device__ __forceinline__ void p2_unpack(ull v, float& lo, float& hi) {
    asm("mov.b64 {%0, %1}, %2;" : "=f"(lo), "=f"(hi) : "l"(v));
}
__device__ __forceinline__ uint32_t pack_h2(float a, float b) {
    __half2 t = __floats2half2_rn(a, b);
    return *reinterpret_cast<uint32_t*>(&t);
}
__device__ __forceinline__ void mma_f16(float* c, uint32_t a0, uint32_t a1,
                                        uint32_t a2, uint32_t a3,
                                        uint32_t b0, uint32_t b1) {
    asm volatile(
        "mma.sync.aligned.m16n8k16.row.col.f32.f16.f16.f32 "
        "{%0,%1,%2,%3}, {%4,%5,%6,%7}, {%8,%9}, {%0,%1,%2,%3};"
        : "+f"(c[0]), "+f"(c[1]), "+f"(c[2]), "+f"(c[3])
        : "r"(a0), "r"(a1), "r"(a2), "r"(a3), "r"(b0), "r"(b1));
}
__device__ __forceinline__ float qred(float v) {
    v += __shfl_xor_sync(0xffffffffu, v, 1);
    v += __shfl_xor_sync(0xffffffffu, v, 2);
    return v;
}
__device__ __forceinline__ float wred32(float v) {
    #pragma unroll
    for (int s = 16; s > 0; s >>= 1) v += __shfl_xor_sync(0xffffffffu, v, s);
    return v;
}
__device__ __forceinline__ ull ldg_ull(const float* p) {
    return *reinterpret_cast<const ull*>(p);
}

// ---------------- merged prep (single-sync reductions) ----------------
__global__ void prep_all(const float* __restrict__ X,
                         const float* __restrict__ W1,
                         const float* __restrict__ b1,
                         const float* __restrict__ W2) {
    if (blockIdx.x < 256) {
        __shared__ float xs[4][DD];
        __shared__ float redh[4][HH];
        __shared__ float redd[4][HH];
        int sub = threadIdx.x >> 6;
        int n = threadIdx.x & 63;
        int i = blockIdx.x * 4 + sub;
        if (n < DD) xs[sub][n] = X[i * DD + n];
        __syncthreads();
        float hs = 0.f, hd = b1[n];
        #pragma unroll
        for (int d = 0; d < DD; d++) {
            float xv = xs[sub][d];
            hs = fmaf(xv, W1[d * HH + n], hs);
            hd = fmaf(xv, W1[(DD + d) * HH + n], hd);
        }
        g_hs[i * HH + n] = hs;
        g_hd[i * HH + n] = hd;
        redh[sub][n] = hs;
        redd[sub][n] = hd;
        __syncthreads();
        int wi = threadIdx.x >> 5, lid = threadIdx.x & 31;
        int s2 = wi & 3;
        const float* src = (wi >= 4) ? redd[s2] : redh[s2];
        float v = src[lid] + src[lid + 32];
        v = wred32(v);
        if (lid == 0) {
            if (wi >= 4) g_dsum[blockIdx.x * 4 + s2] = v;
            else         g_hsum[blockIdx.x * 4 + s2] = v;
        }
    } else {
        #pragma unroll
        for (int e = 0; e < 2; e++) {
            int tt = threadIdx.x + e * 256;
            int lane = tt & 31;
            int kp = (tt >> 5) & 1;
            int nt = tt >> 6;
            int n  = nt * 8 + (lane >> 2);
            int kq = kp * 32 + (lane & 3) * 2;
            uint4 r;
            r.x = pack_h2(W2[kq * HH + n],        W2[(kq + 1) * HH + n]);
            r.y = pack_h2(W2[(kq + 8) * HH + n],  W2[(kq + 9) * HH + n]);
            r.z = pack_h2(W2[(kq + 16) * HH + n], W2[(kq + 17) * HH + n]);
            r.w = pack_h2(W2[(kq + 24) * HH + n], W2[(kq + 25) * HH + n]);
            g_w2f4[tt] = r;
        }
    }
}

// ---------------- prep2: rewrite hd into pair-kernel fragment order ----------------
// Entry idx within blk: idx = rr*256 + ci*32 + lane; lane=(qr<<2)|qc
// value = {hd[blk*16 + rr*8 + qr][c], hd[...][c+1]}, c = (ci>>1)*16 + (ci&1)*8 + qc*2
__global__ void prep_hdf() {
    int blk = blockIdx.x;
    #pragma unroll
    for (int e = 0; e < 2; e++) {
        int idx = threadIdx.x + e * 256;
        int lane = idx & 31;
        int ci = (idx >> 5) & 7;
        int rr = idx >> 8;
        int qr = lane >> 2, qc = lane & 3;
        int j = blk * 16 + rr * 8 + qr;
        int c = (ci >> 1) * 16 + (ci & 1) * 8 + qc * 2;
        g_hdF[blk * 512 + idx] = ldg_ull(g_hd + j * HH + c);
    }
}

// ---------------- main pair kernel: zero smem, zero sync, all reads via L1 ----------------
__global__ __launch_bounds__(128, 4) void pair_kernel(
    const float* __restrict__ g1, const float* __restrict__ be1,
    const float* __restrict__ b2, const float* __restrict__ g2,
    const float* __restrict__ be2, const float* __restrict__ W3,
    const float* __restrict__ b3, float* __restrict__ out) {
    int tid = threadIdx.x;
    int w = tid >> 5, lane = tid & 31;
    int qr = lane >> 2, qc = lane & 3;
    int bx = blockIdx.x, by = blockIdx.y;

    // ---- hd rows in registers, loaded COALESCED from fragment-ordered array ----
    ull dA[8], dB[8];
    {
        const ull* hdF = g_hdF + bx * 512;
        #pragma unroll
        for (int ci = 0; ci < 8; ci++) {
            dA[ci] = hdF[ci * 32 + lane];          // 256B contiguous: 2 wavefronts
            dB[ci] = hdF[256 + ci * 32 + lane];
        }
    }
    const float* hsr0 = g_hs + (by * 8 + w * 2) * HH;
    const float* hsr1 = hsr0 + HH;

    // ---- Phase A: four independent packed sum-of-squares, batched reductions ----
    ull s2p0 = 0ull, s2p1 = 0ull, s2p2 = 0ull, s2p3 = 0ull;
    #pragma unroll
    for (int ci = 0; ci < 8; ci++) {
        int c = (ci >> 1) * 16 + (ci & 1) * 8 + qc * 2;
        ull a0 = ldg_ull(hsr0 + c);
        ull a1 = ldg_ull(hsr1 + c);
        ull x;
        x = p2_add(a0, dA[ci]); s2p0 = p2_fma(x, x, s2p0);
        x = p2_add(a0, dB[ci]); s2p1 = p2_fma(x, x, s2p1);
        x = p2_add(a1, dA[ci]); s2p2 = p2_fma(x, x, s2p2);
        x = p2_add(a1, dB[ci]); s2p3 = p2_fma(x, x, s2p3);
    }
    float lo, hi;
    p2_unpack(s2p0, lo, hi); float q0 = lo + hi;
    p2_unpack(s2p1, lo, hi); float q1 = lo + hi;
    p2_unpack(s2p2, lo, hi); float q2 = lo + hi;
    p2_unpack(s2p3, lo, hi); float q3 = lo + hi;
    q0 = qred(q0); q1 = qred(q1); q2 = qred(q2); q3 = qred(q3);
    float Sv0 = g_hsum[by * 8 + w * 2], Sv1 = g_hsum[by * 8 + w * 2 + 1];
    float Tv1 = g_dsum[bx * 16 + qr],   Tv2 = g_dsum[bx * 16 + qr + 8];
    float mu0 = (Sv0 + Tv1) * (1.f / HH);
    float mu1 = (Sv0 + Tv2) * (1.f / HH);
    float mu2 = (Sv1 + Tv1) * (1.f / HH);
    float mu3 = (Sv1 + Tv2) * (1.f / HH);
    float rs0 = rsqrtf(q0 * (1.f / HH) - mu0 * mu0 + LN_EPS);
    float rs1 = rsqrtf(q1 * (1.f / HH) - mu1 * mu1 + LN_EPS);
    float rs2 = rsqrtf(q2 * (1.f / HH) - mu2 * mu2 + LN_EPS);
    float rs3 = rsqrtf(q3 * (1.f / HH) - mu3 * mu3 + LN_EPS);
    ull rsp0 = p2_pack(rs0, rs0), nmp0 = p2_pack(-mu0 * rs0, -mu0 * rs0);
    ull rsp1 = p2_pack(rs1, rs1), nmp1 = p2_pack(-mu1 * rs1, -mu1 * rs1);
    ull rsp2 = p2_pack(rs2, rs2), nmp2 = p2_pack(-mu2 * rs2, -mu2 * rs2);
    ull rsp3 = p2_pack(rs3, rs3), nmp3 = p2_pack(-mu3 * rs3, -mu3 * rs3);

    // ---- Phase B: apply, column-outer (params loaded once per column, L1-hit) ----
    uint32_t af[2][4][4];
    #pragma unroll
    for (int ci = 0; ci < 8; ci++) {
        int kk = ci >> 1, h = ci & 1;
        int c = kk * 16 + h * 8 + qc * 2;
        ull gp = ldg_ull(g1 + c);
        ull bp = ldg_ull(be1 + c);
        ull a0 = ldg_ull(hsr0 + c);
        ull a1 = ldg_ull(hsr1 + c);
        ull x, v;
        float va, vb;
        x = p2_add(a0, dA[ci]);
        v = p2_fma(p2_fma(x, rsp0, nmp0), gp, bp);
        p2_unpack(v, va, vb);
        af[0][kk][h * 2 + 0] = pack_h2(fmaxf(va, 0.f), fmaxf(vb, 0.f));
        x = p2_add(a0, dB[ci]);
        v = p2_fma(p2_fma(x, rsp1, nmp1), gp, bp);
        p2_unpack(v, va, vb);
        af[0][kk][h * 2 + 1] = pack_h2(fmaxf(va, 0.f), fmaxf(vb, 0.f));
        x = p2_add(a1, dA[ci]);
        v = p2_fma(p2_fma(x, rsp2, nmp2), gp, bp);
        p2_unpack(v, va, vb);
        af[1][kk][h * 2 + 0] = pack_h2(fmaxf(va, 0.f), fmaxf(vb, 0.f));
        x = p2_add(a1, dB[ci]);
        v = p2_fma(p2_fma(x, rsp3, nmp3), gp, bp);
        p2_unpack(v, va, vb);
        af[1][kk][h * 2 + 1] = pack_h2(fmaxf(va, 0.f), fmaxf(vb, 0.f));
    }

    // ---- fused MMA, acc initialized with b2; B-frags direct LDG.128 (L1-hot) ----
    float acc[2][8][4];
    #pragma unroll
    for (int nt = 0; nt < 8; nt++) {
        int c = nt * 8 + qc * 2;
        ull b2p = ldg_ull(b2 + c);
        float bxv, byv;
        p2_unpack(b2p, bxv, byv);
        #pragma unroll
        for (int mt = 0; mt < 2; mt++) {
            acc[mt][nt][0] = bxv; acc[mt][nt][1] = byv;
            acc[mt][nt][2] = bxv; acc[mt][nt][3] = byv;
        }
    }
    #pragma unroll
    for (int nt = 0; nt < 8; nt++) {
        #pragma unroll
        for (int kp = 0; kp < 2; kp++) {
            uint4 B = g_w2f4[(nt * 2 + kp) * 32 + lane];
            int k0 = 2 * kp, k1 = 2 * kp + 1;
            mma_f16(acc[0][nt], af[0][k0][0], af[0][k0][1], af[0][k0][2], af[0][k0][3], B.x, B.y);
            mma_f16(acc[1][nt], af[1][k0][0], af[1][k0][1], af[1][k0][2], af[1][k0][3], B.x, B.y);
            mma_f16(acc[0][nt], af[0][k1][0], af[0][k1][1], af[0][k1][2], af[0][k1][3], B.z, B.w);
            mma_f16(acc[1][nt], af[1][k1][0], af[1][k1][1], af[1][k1][2], af[1][k1][3], B.z, B.w);
        }
    }

    // ---- Epilogue Phase A: LN2 stats for both mtiles, batched reductions ----
    ull ts[2][2][2];
    #pragma unroll
    for (int mt = 0; mt < 2; mt++) {
        ull t0 = 0ull, t1 = 0ull, t2 = 0ull, t3 = 0ull;
        #pragma unroll
        for (int nt = 0; nt < 8; nt++) {
            ull ua = p2_pack(acc[mt][nt][0], acc[mt][nt][1]);
            ull ub = p2_pack(acc[mt][nt][2], acc[mt][nt][3]);
            t0 = p2_add(t0, ua); t1 = p2_fma(ua, ua, t1);
            t2 = p2_add(t2, ub); t3 = p2_fma(ub, ub, t3);
        }
        ts[mt][0][0] = t0; ts[mt][0][1] = t1;
        ts[mt][1][0] = t2; ts[mt][1][1] = t3;
    }
    float tr[2][2][2];
    #pragma unroll
    for (int mt = 0; mt < 2; mt++)
        #pragma unroll
        for (int rr = 0; rr < 2; rr++)
            #pragma unroll
            for (int e = 0; e < 2; e++) {
                p2_unpack(ts[mt][rr][e], lo, hi);
                tr[mt][rr][e] = lo + hi;
            }
    #pragma unroll
    for (int mt = 0; mt < 2; mt++)
        #pragma unroll
        for (int rr = 0; rr < 2; rr++)
            #pragma unroll
            for (int e = 0; e < 2; e++)
                tr[mt][rr][e] = qred(tr[mt][rr][e]);
    ull rp[2][2], np[2][2];
    #pragma unroll
    for (int mt = 0; mt < 2; mt++)
        #pragma unroll
        for (int rr = 0; rr < 2; rr++) {
            float m = tr[mt][rr][0] * (1.f / HH);
            float r = rsqrtf(tr[mt][rr][1] * (1.f / HH) - m * m + LN_EPS);
            rp[mt][rr] = p2_pack(r, r);
            np[mt][rr] = p2_pack(-m * r, -m * r);
        }

    // ---- Epilogue Phase B: nt-outer, params loaded once per column ----
    ull dacc[2][2] = {{0ull, 0ull}, {0ull, 0ull}};
    #pragma unroll
    for (int nt = 0; nt < 8; nt++) {
        int c = nt * 8 + qc * 2;
        ull g2p  = ldg_ull(g2 + c);
        ull be2p = ldg_ull(be2 + c);
        ull w3p  = ldg_ull(W3 + c);
        #pragma unroll
        for (int mt = 0; mt < 2; mt++) {
            float za, zb;
            ull ua = p2_pack(acc[mt][nt][0], acc[mt][nt][1]);
            ull z1 = p2_fma(p2_fma(ua, rp[mt][0], np[mt][0]), g2p, be2p);
            p2_unpack(z1, za, zb);
            dacc[mt][0] = p2_fma(p2_pack(fmaxf(za, 0.f), fmaxf(zb, 0.f)), w3p, dacc[mt][0]);
            ull ub = p2_pack(acc[mt][nt][2], acc[mt][nt][3]);
            ull z2 = p2_fma(p2_fma(ub, rp[mt][1], np[mt][1]), g2p, be2p);
            p2_unpack(z2, za, zb);
            dacc[mt][1] = p2_fma(p2_pack(fmaxf(za, 0.f), fmaxf(zb, 0.f)), w3p, dacc[mt][1]);
        }
    }
    float dv[2][2];
    #pragma unroll
    for (int mt = 0; mt < 2; mt++)
        #pragma unroll
        for (int rr = 0; rr < 2; rr++) {
            p2_unpack(dacc[mt][rr], lo, hi);
            dv[mt][rr] = lo + hi;
        }
    dv[0][0] = qred(dv[0][0]); dv[0][1] = qred(dv[0][1]);
    dv[1][0] = qred(dv[1][0]); dv[1][1] = qred(dv[1][1]);
    if (qc == 0) {
        int j1 = bx * 16 + qr;
        float b3v = b3[0];
        #pragma unroll
        for (int mt = 0; mt < 2; mt++) {
            int i = by * 8 + w * 2 + mt;
            out[i * NN + j1]     = 1.f / (1.f + __expf(-(dv[mt][0] + b3v)));
            out[i * NN + j1 + 8] = 1.f / (1.f + __expf(-(dv[mt][1] + b3v)));
        }
    }
}

// ---------------- launch ----------------
extern "C" void kernel_launch(void* const* d_in, const int* in_sizes, int n_in,
                              void* d_out, int out_size) {
    const float* X   = (const float*)d_in[0];
    const float* W1  = (const float*)d_in[1];
    const float* b1  = (const float*)d_in[2];
    const float* g1  = (const float*)d_in[3];
    const float* be1 = (const float*)d_in[4];
    const float* W2  = (const float*)d_in[5];
    const float* b2  = (const float*)d_in[6];
    const float* g2  = (const float*)d_in[7];
    const float* be2 = (const float*)d_in[8];
    const float* W3  = (const float*)d_in[9];
    const float* b3  = (const float*)d_in[10];
    float* out = (float*)d_out;

    prep_all<<<257, 256>>>(X, W1, b1, W2);
    prep_hdf<<<64, 256>>>();
    dim3 grid(NN / 16, NN / 8);
    pair_kernel<<<grid, 128>>>(g1, be1, b2, g2, be2, W3, b3, out);
}

// round 16
// speedup vs baseline: 1.4231x; 1.0165x over previous
#include <cuda_runtime.h>
#include <cuda_fp16.h>
#include <cstdint>

#define NN 1024
#define DD 32
#define HH 64
#define LN_EPS 1e-5f

typedef unsigned long long ull;

// ---------------- device globals ----------------
__device__ float g_hs[NN * HH];          // X @ W1[:32]
__device__ float g_hsum[NN];             // row sums of hs
__device__ float g_dsum[NN];             // row sums of hd
__device__ uint4 g_w2f4[8 * 2 * 32];     // fp16 W2 B-frags: [nt][kp][lane]
__device__ ull   g_hdF[64 * 2 * 8 * 32]; // hd in pair-kernel fragment order: [blk][rr][ci][lane]

// ---------------- packed f32x2 helpers ----------------
__device__ __forceinline__ ull p2_add(ull a, ull b) {
    ull r; asm("add.rn.f32x2 %0, %1, %2;" : "=l"(r) : "l"(a), "l"(b)); return r;
}
__device__ __forceinline__ ull p2_fma(ull a, ull b, ull c) {
    ull r; asm("fma.rn.f32x2 %0, %1, %2, %3;" : "=l"(r) : "l"(a), "l"(b), "l"(c)); return r;
}
__device__ __forceinline__ ull p2_pack(float lo, float hi) {
    ull r; asm("mov.b64 %0, {%1, %2};" : "=l"(r) : "f"(lo), "f"(hi)); return r;
}
__device__ __forceinline__ void p2_unpack(ull v, float& lo, float& hi) {
    asm("mov.b64 {%0, %1}, %2;" : "=f"(lo), "=f"(hi) : "l"(v));
}
__device__ __forceinline__ uint32_t pack_h2(float a, float b) {
    __half2 t = __floats2half2_rn(a, b);
    return *reinterpret_cast<uint32_t*>(&t);
}
__device__ __forceinline__ void mma_f16(float* c, uint32_t a0, uint32_t a1,
                                        uint32_t a2, uint32_t a3,
                                        uint32_t b0, uint32_t b1) {
    asm volatile(
        "mma.sync.aligned.m16n8k16.row.col.f32.f16.f16.f32 "
        "{%0,%1,%2,%3}, {%4,%5,%6,%7}, {%8,%9}, {%0,%1,%2,%3};"
        : "+f"(c[0]), "+f"(c[1]), "+f"(c[2]), "+f"(c[3])
        : "r"(a0), "r"(a1), "r"(a2), "r"(a3), "r"(b0), "r"(b1));
}
__device__ __forceinline__ float qred(float v) {
    v += __shfl_xor_sync(0xffffffffu, v, 1);
    v += __shfl_xor_sync(0xffffffffu, v, 2);
    return v;
}
__device__ __forceinline__ float wred32(float v) {
    #pragma unroll
    for (int s = 16; s > 0; s >>= 1) v += __shfl_xor_sync(0xffffffffu, v, s);
    return v;
}
__device__ __forceinline__ ull ldg_ull(const float* p) {
    return *reinterpret_cast<const ull*>(p);
}

// ---------------- fused prep: 16-row tiles, hdF written straight from smem ----------------
__global__ void prep_all(const float* __restrict__ X,
                         const float* __restrict__ W1,
                         const float* __restrict__ b1,
                         const float* __restrict__ W2) {
    if (blockIdx.x < 64) {
        __shared__ float xs[16][DD];
        __shared__ float sh[16][HH];
        __shared__ float sd[16][HH];
        int t = threadIdx.x;
        int blk = blockIdx.x;
        #pragma unroll
        for (int e = 0; e < 2; e++) {
            int idx = t + e * 256;              // 512 floats
            int r = idx >> 5, c = idx & 31;
            xs[r][c] = X[(blk * 16 + r) * DD + c];
        }
        __syncthreads();
        int n = t & 63;
        int rg = t >> 6;                        // 0..3
        float b1n = b1[n];
        // 4 independent dot-chain pairs per thread (ILP)
        float hsv[4], hdv[4];
        #pragma unroll
        for (int q = 0; q < 4; q++) { hsv[q] = 0.f; hdv[q] = b1n; }
        #pragma unroll
        for (int d = 0; d < DD; d++) {
            float ws = W1[d * HH + n];
            float wd = W1[(DD + d) * HH + n];
            #pragma unroll
            for (int q = 0; q < 4; q++) {
                float xv = xs[rg * 4 + q][d];
                hsv[q] = fmaf(xv, ws, hsv[q]);
                hdv[q] = fmaf(xv, wd, hdv[q]);
            }
        }
        #pragma unroll
        for (int q = 0; q < 4; q++) {
            int r = rg * 4 + q;
            sh[r][n] = hsv[q];
            sd[r][n] = hdv[q];
            g_hs[(blk * 16 + r) * HH + n] = hsv[q];
        }
        __syncthreads();
        // 32 row reductions with 8 warps x 4 (identical order to previous rounds)
        int wi = t >> 5, lid = t & 31;
        #pragma unroll
        for (int e = 0; e < 4; e++) {
            int idx = wi + e * 8;               // 0..31
            const float* src = (idx < 16) ? sh[idx] : sd[idx - 16];
            float v = src[lid] + src[lid + 32];
            v = wred32(v);
            if (lid == 0) {
                if (idx < 16) g_hsum[blk * 16 + idx] = v;
                else          g_dsum[blk * 16 + idx - 16] = v;
            }
        }
        // write g_hdF in pair-kernel fragment order, straight from smem
        #pragma unroll
        for (int e = 0; e < 2; e++) {
            int idx = t + e * 256;              // 512 ull entries
            int lane = idx & 31;
            int ci = (idx >> 5) & 7;
            int rr = idx >> 8;
            int qr2 = lane >> 2, qc2 = lane & 3;
            int row = rr * 8 + qr2;
            int c = (ci >> 1) * 16 + (ci & 1) * 8 + qc2 * 2;
            g_hdF[blk * 512 + idx] = p2_pack(sd[row][c], sd[row][c + 1]);
        }
    } else {
        // W2 -> uint4 B-frags (unchanged)
        #pragma unroll
        for (int e = 0; e < 2; e++) {
            int tt = threadIdx.x + e * 256;
            int lane = tt & 31;
            int kp = (tt >> 5) & 1;
            int nt = tt >> 6;
            int n  = nt * 8 + (lane >> 2);
            int kq = kp * 32 + (lane & 3) * 2;
            uint4 r;
            r.x = pack_h2(W2[kq * HH + n],        W2[(kq + 1) * HH + n]);
            r.y = pack_h2(W2[(kq + 8) * HH + n],  W2[(kq + 9) * HH + n]);
            r.z = pack_h2(W2[(kq + 16) * HH + n], W2[(kq + 17) * HH + n]);
            r.w = pack_h2(W2[(kq + 24) * HH + n], W2[(kq + 25) * HH + n]);
            g_w2f4[tt] = r;
        }
    }
}

// ---------------- main pair kernel: unchanged from R15 (protect the win) ----------------
__global__ __launch_bounds__(128, 4) void pair_kernel(
    const float* __restrict__ g1, const float* __restrict__ be1,
    const float* __restrict__ b2, const float* __restrict__ g2,
    const float* __restrict__ be2, const float* __restrict__ W3,
    const float* __restrict__ b3, float* __restrict__ out) {
    int tid = threadIdx.x;
    int w = tid >> 5, lane = tid & 31;
    int qr = lane >> 2, qc = lane & 3;
    int bx = blockIdx.x, by = blockIdx.y;

    ull dA[8], dB[8];
    {
        const ull* hdF = g_hdF + bx * 512;
        #pragma unroll
        for (int ci = 0; ci < 8; ci++) {
            dA[ci] = hdF[ci * 32 + lane];
            dB[ci] = hdF[256 + ci * 32 + lane];
        }
    }
    const float* hsr0 = g_hs + (by * 8 + w * 2) * HH;
    const float* hsr1 = hsr0 + HH;

    ull s2p0 = 0ull, s2p1 = 0ull, s2p2 = 0ull, s2p3 = 0ull;
    #pragma unroll
    for (int ci = 0; ci < 8; ci++) {
        int c = (ci >> 1) * 16 + (ci & 1) * 8 + qc * 2;
        ull a0 = ldg_ull(hsr0 + c);
        ull a1 = ldg_ull(hsr1 + c);
        ull x;
        x = p2_add(a0, dA[ci]); s2p0 = p2_fma(x, x, s2p0);
        x = p2_add(a0, dB[ci]); s2p1 = p2_fma(x, x, s2p1);
        x = p2_add(a1, dA[ci]); s2p2 = p2_fma(x, x, s2p2);
        x = p2_add(a1, dB[ci]); s2p3 = p2_fma(x, x, s2p3);
    }
    float lo, hi;
    p2_unpack(s2p0, lo, hi); float q0 = lo + hi;
    p2_unpack(s2p1, lo, hi); float q1 = lo + hi;
    p2_unpack(s2p2, lo, hi); float q2 = lo + hi;
    p2_unpack(s2p3, lo, hi); float q3 = lo + hi;
    q0 = qred(q0); q1 = qred(q1); q2 = qred(q2); q3 = qred(q3);
    float Sv0 = g_hsum[by * 8 + w * 2], Sv1 = g_hsum[by * 8 + w * 2 + 1];
    float Tv1 = g_dsum[bx * 16 + qr],   Tv2 = g_dsum[bx * 16 + qr + 8];
    float mu0 = (Sv0 + Tv1) * (1.f / HH);
    float mu1 = (Sv0 + Tv2) * (1.f / HH);
    float mu2 = (Sv1 + Tv1) * (1.f / HH);
    float mu3 = (Sv1 + Tv2) * (1.f / HH);
    float rs0 = rsqrtf(q0 * (1.f / HH) - mu0 * mu0 + LN_EPS);
    float rs1 = rsqrtf(q1 * (1.f / HH) - mu1 * mu1 + LN_EPS);
    float rs2 = rsqrtf(q2 * (1.f / HH) - mu2 * mu2 + LN_EPS);
    float rs3 = rsqrtf(q3 * (1.f / HH) - mu3 * mu3 + LN_EPS);
    ull rsp0 = p2_pack(rs0, rs0), nmp0 = p2_pack(-mu0 * rs0, -mu0 * rs0);
    ull rsp1 = p2_pack(rs1, rs1), nmp1 = p2_pack(-mu1 * rs1, -mu1 * rs1);
    ull rsp2 = p2_pack(rs2, rs2), nmp2 = p2_pack(-mu2 * rs2, -mu2 * rs2);
    ull rsp3 = p2_pack(rs3, rs3), nmp3 = p2_pack(-mu3 * rs3, -mu3 * rs3);

    uint32_t af[2][4][4];
    #pragma unroll
    for (int ci = 0; ci < 8; ci++) {
        int kk = ci >> 1, h = ci & 1;
        int c = kk * 16 + h * 8 + qc * 2;
        ull gp = ldg_ull(g1 + c);
        ull bp = ldg_ull(be1 + c);
        ull a0 = ldg_ull(hsr0 + c);
        ull a1 = ldg_ull(hsr1 + c);
        ull x, v;
        float va, vb;
        x = p2_add(a0, dA[ci]);
        v = p2_fma(p2_fma(x, rsp0, nmp0), gp, bp);
        p2_unpack(v, va, vb);
        af[0][kk][h * 2 + 0] = pack_h2(fmaxf(va, 0.f), fmaxf(vb, 0.f));
        x = p2_add(a0, dB[ci]);
        v = p2_fma(p2_fma(x, rsp1, nmp1), gp, bp);
        p2_unpack(v, va, vb);
        af[0][kk][h * 2 + 1] = pack_h2(fmaxf(va, 0.f), fmaxf(vb, 0.f));
        x = p2_add(a1, dA[ci]);
        v = p2_fma(p2_fma(x, rsp2, nmp2), gp, bp);
        p2_unpack(v, va, vb);
        af[1][kk][h * 2 + 0] = pack_h2(fmaxf(va, 0.f), fmaxf(vb, 0.f));
        x = p2_add(a1, dB[ci]);
        v = p2_fma(p2_fma(x, rsp3, nmp3), gp, bp);
        p2_unpack(v, va, vb);
        af[1][kk][h * 2 + 1] = pack_h2(fmaxf(va, 0.f), fmaxf(vb, 0.f));
    }

    float acc[2][8][4];
    #pragma unroll
    for (int nt = 0; nt < 8; nt++) {
        int c = nt * 8 + qc * 2;
        ull b2p = ldg_ull(b2 + c);
        float bxv, byv;
        p2_unpack(b2p, bxv, byv);
        #pragma unroll
        for (int mt = 0; mt < 2; mt++) {
            acc[mt][nt][0] = bxv; acc[mt][nt][1] = byv;
            acc[mt][nt][2] = bxv; acc[mt][nt][3] = byv;
        }
    }
    #pragma unroll
    for (int nt = 0; nt < 8; nt++) {
        #pragma unroll
        for (int kp = 0; kp < 2; kp++) {
            uint4 B = g_w2f4[(nt * 2 + kp) * 32 + lane];
            int k0 = 2 * kp, k1 = 2 * kp + 1;
            mma_f16(acc[0][nt], af[0][k0][0], af[0][k0][1], af[0][k0][2], af[0][k0][3], B.x, B.y);
            mma_f16(acc[1][nt], af[1][k0][0], af[1][k0][1], af[1][k0][2], af[1][k0][3], B.x, B.y);
            mma_f16(acc[0][nt], af[0][k1][0], af[0][k1][1], af[0][k1][2], af[0][k1][3], B.z, B.w);
            mma_f16(acc[1][nt], af[1][k1][0], af[1][k1][1], af[1][k1][2], af[1][k1][3], B.z, B.w);
        }
    }

    ull ts[2][2][2];
    #pragma unroll
    for (int mt = 0; mt < 2; mt++) {
        ull t0 = 0ull, t1 = 0ull, t2 = 0ull, t3 = 0ull;
        #pragma unroll
        for (int nt = 0; nt < 8; nt++) {
            ull ua = p2_pack(acc[mt][nt][0], acc[mt][nt][1]);
            ull ub = p2_pack(acc[mt][nt][2], acc[mt][nt][3]);
            t0 = p2_add(t0, ua); t1 = p2_fma(ua, ua, t1);
            t2 = p2_add(t2, ub); t3 = p2_fma(ub, ub, t3);
        }
        ts[mt][0][0] = t0; ts[mt][0][1] = t1;
        ts[mt][1][0] = t2; ts[mt][1][1] = t3;
    }
    float tr[2][2][2];
    #pragma unroll
    for (int mt = 0; mt < 2; mt++)
        #pragma unroll
        for (int rr = 0; rr < 2; rr++)
            #pragma unroll
            for (int e = 0; e < 2; e++) {
                p2_unpack(ts[mt][rr][e], lo, hi);
                tr[mt][rr][e] = lo + hi;
            }
    #pragma unroll
    for (int mt = 0; mt < 2; mt++)
        #pragma unroll
        for (int rr = 0; rr < 2; rr++)
            #pragma unroll
            for (int e = 0; e < 2; e++)
                tr[mt][rr][e] = qred(tr[mt][rr][e]);
    ull rp[2][2], np[2][2];
    #pragma unroll
    for (int mt = 0; mt < 2; mt++)
        #pragma unroll
        for (int rr = 0; rr < 2; rr++) {
            float m = tr[mt][rr][0] * (1.f / HH);
            float r = rsqrtf(tr[mt][rr][1] * (1.f / HH) - m * m + LN_EPS);
            rp[mt][rr] = p2_pack(r, r);
            np[mt][rr] = p2_pack(-m * r, -m * r);
        }

    ull dacc[2][2] = {{0ull, 0ull}, {0ull, 0ull}};
    #pragma unroll
    for (int nt = 0; nt < 8; nt++) {
        int c = nt * 8 + qc * 2;
        ull g2p  = ldg_ull(g2 + c);
        ull be2p = ldg_ull(be2 + c);
        ull w3p  = ldg_ull(W3 + c);
        #pragma unroll
        for (int mt = 0; mt < 2; mt++) {
            float za, zb;
            ull ua = p2_pack(acc[mt][nt][0], acc[mt][nt][1]);
            ull z1 = p2_fma(p2_fma(ua, rp[mt][0], np[mt][0]), g2p, be2p);
            p2_unpack(z1, za, zb);
            dacc[mt][0] = p2_fma(p2_pack(fmaxf(za, 0.f), fmaxf(zb, 0.f)), w3p, dacc[mt][0]);
            ull ub = p2_pack(acc[mt][nt][2], acc[mt][nt][3]);
            ull z2 = p2_fma(p2_fma(ub, rp[mt][1], np[mt][1]), g2p, be2p);
            p2_unpack(z2, za, zb);
            dacc[mt][1] = p2_fma(p2_pack(fmaxf(za, 0.f), fmaxf(zb, 0.f)), w3p, dacc[mt][1]);
        }
    }
    float dv[2][2];
    #pragma unroll
    for (int mt = 0; mt < 2; mt++)
        #pragma unroll
        for (int rr = 0; rr < 2; rr++) {
            p2_unpack(dacc[mt][rr], lo, hi);
            dv[mt][rr] = lo + hi;
        }
    dv[0][0] = qred(dv[0][0]); dv[0][1] = qred(dv[0][1]);
    dv[1][0] = qred(dv[1][0]); dv[1][1] = qred(dv[1][1]);
    if (qc == 0) {
        int j1 = bx * 16 + qr;
        float b3v = b3[0];
        #pragma unroll
        for (int mt = 0; mt < 2; mt++) {
            int i = by * 8 + w * 2 + mt;
            out[i * NN + j1]     = 1.f / (1.f + __expf(-(dv[mt][0] + b3v)));
            out[i * NN + j1 + 8] = 1.f / (1.f + __expf(-(dv[mt][1] + b3v)));
        }
    }
}

// ---------------- launch ----------------
extern "C" void kernel_launch(void* const* d_in, const int* in_sizes, int n_in,
                              void* d_out, int out_size) {
    const float* X   = (const float*)d_in[0];
    const float* W1  = (const float*)d_in[1];
    const float* b1  = (const float*)d_in[2];
    const float* g1  = (const float*)d_in[3];
    const float* be1 = (const float*)d_in[4];
    const float* W2  = (const float*)d_in[5];
    const float* b2  = (const float*)d_in[6];
    const float* g2  = (const float*)d_in[7];
    const float* be2 = (const float*)d_in[8];
    const float* W3  = (const float*)d_in[9];
    const float* b3  = (const float*)d_in[10];
    float* out = (float*)d_out;

    prep_all<<<65, 256>>>(X, W1, b1, W2);
    dim3 grid(NN / 16, NN / 8);
    pair_kernel<<<grid, 128>>>(g1, be1, b2, g2, be2, W3, b3, out);
}